// round 3
// baseline (speedup 1.0000x reference)
#include <cuda_runtime.h>
#include <cuda_bf16.h>
#include <math.h>

// ---------------- problem constants ----------------
#define EMB        300
#define C4         75          // EMB / 4 (float4 chunks)
#define NLAYERS    5
#define NGRAPH     4096
#define ATOM_F     9
#define ATOM_V     128
#define BOND_V     8
#define BN_EPS     1e-5f
#define NMAX       100000
#define EMAX       250000

// ---------------- device scratch (allocation-free) ----------------
__device__ __align__(16) float g_h     [(size_t)NMAX * EMB];      // 120 MB
__device__ __align__(16) float g_agg   [(size_t)NMAX * EMB];      // 120 MB
__device__ __align__(16) float g_t1    [(size_t)NMAX * 2 * EMB];  // 240 MB
__device__ __align__(16) float g_vn    [(size_t)NGRAPH * EMB];
__device__ __align__(16) float g_pooled[(size_t)NGRAPH * EMB];
__device__ __align__(16) float g_vnt   [(size_t)NGRAPH * 2 * EMB];
__device__            float g_counts[NGRAPH];

// ---------------- atom encoder: h[n,:] = sum_f atom_emb[f, x[n,f], :] ----------------
__global__ void k_atom_encode(const int* __restrict__ x,
                              const float* __restrict__ atom_emb,
                              float* __restrict__ h, int N) {
    int idx = blockIdx.x * blockDim.x + threadIdx.x;
    if (idx >= N * C4) return;
    int n = idx / C4, c = idx % C4;
    float4 acc = make_float4(0.f, 0.f, 0.f, 0.f);
#pragma unroll
    for (int f = 0; f < ATOM_F; f++) {
        int a = x[n * ATOM_F + f];
        float4 v = *(const float4*)(atom_emb + ((size_t)(f * ATOM_V + a)) * EMB + c * 4);
        acc.x += v.x; acc.y += v.y; acc.z += v.z; acc.w += v.w;
    }
    *(float4*)(h + (size_t)n * EMB + c * 4) = acc;
}

// ---------------- vn broadcast init: vn[g,:] = vn_emb[0,:] ----------------
__global__ void k_vn_init(const float* __restrict__ vn_emb, float* __restrict__ vn) {
    int idx = blockIdx.x * blockDim.x + threadIdx.x;
    if (idx >= NGRAPH * EMB) return;
    vn[idx] = vn_emb[idx % EMB];
}

// ---------------- pooled init: pooled = vn ----------------
__global__ void k_pool_init(const float* __restrict__ vn, float* __restrict__ pooled) {
    int idx = blockIdx.x * blockDim.x + threadIdx.x;
    if (idx >= NGRAPH * EMB) return;
    pooled[idx] = vn[idx];
}

// ---------------- fused: h += vn[batch]; agg = (1+eps)*h; pooled += h (opt) ----------------
__global__ void k_vnadd_agg(float* __restrict__ h, float* __restrict__ agg,
                            const float* __restrict__ vn, const int* __restrict__ batch,
                            float* __restrict__ pooled, const float* __restrict__ gin_eps,
                            int layer, int do_pool, int N) {
    int idx = blockIdx.x * blockDim.x + threadIdx.x;
    if (idx >= N * C4) return;
    int n = idx / C4, c = idx % C4;
    int b = batch[n];
    float oe = 1.f + gin_eps[layer];
    float4 hv = *(float4*)(h + (size_t)n * EMB + c * 4);
    float4 vv = *(const float4*)(vn + (size_t)b * EMB + c * 4);
    hv.x += vv.x; hv.y += vv.y; hv.z += vv.z; hv.w += vv.w;
    *(float4*)(h + (size_t)n * EMB + c * 4) = hv;
    float4 av = make_float4(hv.x * oe, hv.y * oe, hv.z * oe, hv.w * oe);
    *(float4*)(agg + (size_t)n * EMB + c * 4) = av;
    if (do_pool) {
        float* dst = pooled + (size_t)b * EMB + c * 4;
        atomicAdd(dst + 0, hv.x);
        atomicAdd(dst + 1, hv.y);
        atomicAdd(dst + 2, hv.z);
        atomicAdd(dst + 3, hv.w);
    }
}

// ---------------- edge messages: agg[col] += relu(h[row] + bond_emb(edge_attr)) ----------------
__global__ void k_edge_scatter(const float* __restrict__ h, float* __restrict__ agg,
                               const int* __restrict__ ei, const int* __restrict__ ea,
                               const float* __restrict__ bond_emb, int E) {
    int idx = blockIdx.x * blockDim.x + threadIdx.x;
    if (idx >= E * C4) return;
    int e = idx / C4, c = idx % C4;
    int row = ei[e];
    int col = ei[E + e];
    int a0 = ea[e * 3 + 0];
    int a1 = ea[e * 3 + 1];
    int a2 = ea[e * 3 + 2];
    float4 hv = *(const float4*)(h + (size_t)row * EMB + c * 4);
    float4 b0 = *(const float4*)(bond_emb + (size_t)(0 * BOND_V + a0) * EMB + c * 4);
    float4 b1 = *(const float4*)(bond_emb + (size_t)(1 * BOND_V + a1) * EMB + c * 4);
    float4 b2 = *(const float4*)(bond_emb + (size_t)(2 * BOND_V + a2) * EMB + c * 4);
    float mx = fmaxf(hv.x + b0.x + b1.x + b2.x, 0.f);
    float my = fmaxf(hv.y + b0.y + b1.y + b2.y, 0.f);
    float mz = fmaxf(hv.z + b0.z + b1.z + b2.z, 0.f);
    float mw = fmaxf(hv.w + b0.w + b1.w + b2.w, 0.f);
    float* dst = agg + (size_t)col * EMB + c * 4;
    atomicAdd(dst + 0, mx);
    atomicAdd(dst + 1, my);
    atomicAdd(dst + 2, mz);
    atomicAdd(dst + 3, mw);
}

// ---------------- SGEMM with fused bias + BatchNorm(eval) + optional ReLU ----------------
// out[M,Nc] = op( bn( A[M,K] @ W[K,Nc] + bias ) ), bn folded to y = v*s + off
#define BM 128
#define BN 64
#define BK 16
#define TM 8
#define TN 4
__global__ __launch_bounds__(256, 2)
void k_gemm_bn(const float* __restrict__ A, const float* __restrict__ W,
               const float* __restrict__ bias,
               const float* __restrict__ bng, const float* __restrict__ bnb,
               const float* __restrict__ bnm, const float* __restrict__ bnv,
               float* __restrict__ out, int M, int K, int Nc, int do_relu) {
    __shared__ float As[BK][BM + 4];
    __shared__ float Bs[BK][BN];

    const int tid = threadIdx.x;              // 256 threads
    const int tx = tid % (BN / TN);           // 0..15
    const int ty = tid / (BN / TN);           // 0..15
    const int row0 = blockIdx.y * BM;
    const int col0 = blockIdx.x * BN;

    float acc[TM][TN];
#pragma unroll
    for (int i = 0; i < TM; i++)
#pragma unroll
        for (int j = 0; j < TN; j++) acc[i][j] = 0.f;

    for (int k0 = 0; k0 < K; k0 += BK) {
        // load A tile: BM x BK (2048 elems / 256 thr = 8 each), store transposed
#pragma unroll
        for (int i = 0; i < (BM * BK) / 256; i++) {
            int flat = tid + i * 256;
            int m = flat / BK, kk = flat % BK;
            int gm = row0 + m, gk = k0 + kk;
            As[kk][m] = (gm < M && gk < K) ? A[(size_t)gm * K + gk] : 0.f;
        }
        // load B tile: BK x BN (1024 / 256 = 4 each)
#pragma unroll
        for (int i = 0; i < (BK * BN) / 256; i++) {
            int flat = tid + i * 256;
            int kk = flat / BN, n = flat % BN;
            int gk = k0 + kk, gn = col0 + n;
            Bs[kk][n] = (gk < K && gn < Nc) ? W[(size_t)gk * Nc + gn] : 0.f;
        }
        __syncthreads();
#pragma unroll
        for (int kk = 0; kk < BK; kk++) {
            float a[TM], b[TN];
#pragma unroll
            for (int i = 0; i < TM; i++) a[i] = As[kk][ty * TM + i];
#pragma unroll
            for (int j = 0; j < TN; j++) b[j] = Bs[kk][tx * TN + j];
#pragma unroll
            for (int i = 0; i < TM; i++)
#pragma unroll
                for (int j = 0; j < TN; j++) acc[i][j] = fmaf(a[i], b[j], acc[i][j]);
        }
        __syncthreads();
    }

    // epilogue: bias + BN (+ ReLU)
#pragma unroll
    for (int j = 0; j < TN; j++) {
        int gn = col0 + tx * TN + j;
        if (gn >= Nc) continue;
        float s = bng[gn] * rsqrtf(bnv[gn] + BN_EPS);
        float off = bnb[gn] - bnm[gn] * s;
        float bi = bias[gn];
#pragma unroll
        for (int i = 0; i < TM; i++) {
            int gm = row0 + ty * TM + i;
            if (gm < M) {
                float v = (acc[i][j] + bi) * s + off;
                if (do_relu) v = fmaxf(v, 0.f);
                out[(size_t)gm * Nc + gn] = v;
            }
        }
    }
}

// ---------------- final mean pool ----------------
__global__ void k_final_zero(float* __restrict__ out, float* __restrict__ counts) {
    int idx = blockIdx.x * blockDim.x + threadIdx.x;
    if (idx < NGRAPH * EMB) out[idx] = 0.f;
    if (idx < NGRAPH) counts[idx] = 0.f;
}
__global__ void k_final_acc(const float* __restrict__ h, const int* __restrict__ batch,
                            float* __restrict__ out, float* __restrict__ counts, int N) {
    int idx = blockIdx.x * blockDim.x + threadIdx.x;
    if (idx >= N * C4) return;
    int n = idx / C4, c = idx % C4;
    int b = batch[n];
    float4 hv = *(const float4*)(h + (size_t)n * EMB + c * 4);
    float* dst = out + (size_t)b * EMB + c * 4;
    atomicAdd(dst + 0, hv.x);
    atomicAdd(dst + 1, hv.y);
    atomicAdd(dst + 2, hv.z);
    atomicAdd(dst + 3, hv.w);
    if (c == 0) atomicAdd(counts + b, 1.f);
}
__global__ void k_final_div(float* __restrict__ out, const float* __restrict__ counts) {
    int idx = blockIdx.x * blockDim.x + threadIdx.x;
    if (idx >= NGRAPH * EMB) return;
    int g = idx / EMB;
    out[idx] /= fmaxf(counts[g], 1.f);
}

// ---------------- launch ----------------
static inline dim3 gemm_grid(int M, int Nc) {
    return dim3((Nc + BN - 1) / BN, (M + BM - 1) / BM);
}

extern "C" void kernel_launch(void* const* d_in, const int* in_sizes, int n_in,
                              void* d_out, int out_size) {
    const int*   x        = (const int*)  d_in[0];
    const int*   ei       = (const int*)  d_in[1];
    const int*   ea       = (const int*)  d_in[2];
    const int*   batch    = (const int*)  d_in[3];
    const float* atom_emb = (const float*)d_in[4];
    const float* bond_emb = (const float*)d_in[5];
    const float* vn_emb   = (const float*)d_in[6];
    const float* gin_eps  = (const float*)d_in[7];
    const float* gin_W1   = (const float*)d_in[8];
    const float* gin_b1   = (const float*)d_in[9];
    const float* gin_bn1_g= (const float*)d_in[10];
    const float* gin_bn1_b= (const float*)d_in[11];
    const float* gin_bn1_m= (const float*)d_in[12];
    const float* gin_bn1_v= (const float*)d_in[13];
    const float* gin_W2   = (const float*)d_in[14];
    const float* gin_b2   = (const float*)d_in[15];
    const float* bn_g     = (const float*)d_in[16];
    const float* bn_b     = (const float*)d_in[17];
    const float* bn_m     = (const float*)d_in[18];
    const float* bn_v     = (const float*)d_in[19];
    const float* vn_W1    = (const float*)d_in[20];
    const float* vn_b1    = (const float*)d_in[21];
    const float* vn_bn1_g = (const float*)d_in[22];
    const float* vn_bn1_b = (const float*)d_in[23];
    const float* vn_bn1_m = (const float*)d_in[24];
    const float* vn_bn1_v = (const float*)d_in[25];
    const float* vn_W2    = (const float*)d_in[26];
    const float* vn_b2    = (const float*)d_in[27];
    const float* vn_bn2_g = (const float*)d_in[28];
    const float* vn_bn2_b = (const float*)d_in[29];
    const float* vn_bn2_m = (const float*)d_in[30];
    const float* vn_bn2_v = (const float*)d_in[31];

    const int N = in_sizes[0] / ATOM_F;   // 100000
    const int E = in_sizes[1] / 2;        // 250000
    float* out = (float*)d_out;

    float *h, *agg, *t1, *vn, *pooled, *vnt, *counts;
    cudaGetSymbolAddress((void**)&h,      g_h);
    cudaGetSymbolAddress((void**)&agg,    g_agg);
    cudaGetSymbolAddress((void**)&t1,     g_t1);
    cudaGetSymbolAddress((void**)&vn,     g_vn);
    cudaGetSymbolAddress((void**)&pooled, g_pooled);
    cudaGetSymbolAddress((void**)&vnt,    g_vnt);
    cudaGetSymbolAddress((void**)&counts, g_counts);

    const int T = 256;
    const int gN  = (N * C4 + T - 1) / T;
    const int gE  = (E * C4 + T - 1) / T;
    const int gVN = (NGRAPH * EMB + T - 1) / T;

    // encode + vn init
    k_atom_encode<<<gN, T>>>(x, atom_emb, h, N);
    k_vn_init<<<gVN, T>>>(vn_emb, vn);

    for (int l = 0; l < NLAYERS; l++) {
        const int do_pool = (l < NLAYERS - 1);
        if (do_pool) k_pool_init<<<gVN, T>>>(vn, pooled);
        // h += vn[batch]; agg = (1+eps)*h; pooled += h
        k_vnadd_agg<<<gN, T>>>(h, agg, vn, batch, pooled, gin_eps, l, do_pool, N);
        // agg += scatter-add relu(h[row] + bond_emb)
        k_edge_scatter<<<gE, T>>>(h, agg, ei, ea, bond_emb, E);
        // t1 = relu(bn1(agg @ W1 + b1))  [N, 600]
        k_gemm_bn<<<gemm_grid(N, 2 * EMB), 256>>>(
            agg, gin_W1 + (size_t)l * EMB * 2 * EMB, gin_b1 + l * 2 * EMB,
            gin_bn1_g + l * 2 * EMB, gin_bn1_b + l * 2 * EMB,
            gin_bn1_m + l * 2 * EMB, gin_bn1_v + l * 2 * EMB,
            t1, N, EMB, 2 * EMB, 1);
        // h = bn(t1 @ W2 + b2) (+ relu if not last)  [N, 300]
        k_gemm_bn<<<gemm_grid(N, EMB), 256>>>(
            t1, gin_W2 + (size_t)l * 2 * EMB * EMB, gin_b2 + l * EMB,
            bn_g + l * EMB, bn_b + l * EMB, bn_m + l * EMB, bn_v + l * EMB,
            h, N, 2 * EMB, EMB, do_pool ? 1 : 0);
        if (do_pool) {
            // vn MLP: vnt = relu(bn1(pooled @ vn_W1 + b1)); vn = relu(bn2(vnt @ vn_W2 + b2))
            k_gemm_bn<<<gemm_grid(NGRAPH, 2 * EMB), 256>>>(
                pooled, vn_W1 + (size_t)l * EMB * 2 * EMB, vn_b1 + l * 2 * EMB,
                vn_bn1_g + l * 2 * EMB, vn_bn1_b + l * 2 * EMB,
                vn_bn1_m + l * 2 * EMB, vn_bn1_v + l * 2 * EMB,
                vnt, NGRAPH, EMB, 2 * EMB, 1);
            k_gemm_bn<<<gemm_grid(NGRAPH, EMB), 256>>>(
                vnt, vn_W2 + (size_t)l * 2 * EMB * EMB, vn_b2 + l * EMB,
                vn_bn2_g + l * EMB, vn_bn2_b + l * EMB,
                vn_bn2_m + l * EMB, vn_bn2_v + l * EMB,
                vn, NGRAPH, 2 * EMB, EMB, 1);
        }
    }

    // global mean pool
    k_final_zero<<<gVN, T>>>(out, counts);
    k_final_acc<<<gN, T>>>(h, batch, out, counts, N);
    k_final_div<<<gVN, T>>>(out, counts);
}

// round 4
// speedup vs baseline: 1.1559x; 1.1559x over previous
#include <cuda_runtime.h>
#include <cuda_bf16.h>
#include <math.h>

// ---------------- problem constants ----------------
#define EMB        300
#define C4         75          // EMB / 4 (float4 chunks)
#define NLAYERS    5
#define NGRAPH     4096
#define ATOM_F     9
#define ATOM_V     128
#define BOND_V     8
#define BN_EPS     1e-5f
#define NMAX       100000
#define EMAX       250000

// ---------------- device scratch (allocation-free) ----------------
__device__ __align__(16) float g_h     [(size_t)NMAX * EMB];      // 120 MB
__device__ __align__(16) float g_agg   [(size_t)NMAX * EMB];      // 120 MB
__device__ __align__(16) float g_t1    [(size_t)NMAX * 2 * EMB];  // 240 MB
__device__ __align__(16) float g_vn    [(size_t)NGRAPH * EMB];
__device__ __align__(16) float g_pooled[(size_t)NGRAPH * EMB];
__device__ __align__(16) float g_vnt   [(size_t)NGRAPH * 2 * EMB];
__device__            float g_counts[NGRAPH];

// ---------------- atom encoder: h[n,:] = sum_f atom_emb[f, x[n,f], :] ----------------
__global__ void k_atom_encode(const int* __restrict__ x,
                              const float* __restrict__ atom_emb,
                              float* __restrict__ h, int N) {
    int idx = blockIdx.x * blockDim.x + threadIdx.x;
    if (idx >= N * C4) return;
    int n = idx / C4, c = idx % C4;
    float4 acc = make_float4(0.f, 0.f, 0.f, 0.f);
#pragma unroll
    for (int f = 0; f < ATOM_F; f++) {
        int a = x[n * ATOM_F + f];
        float4 v = *(const float4*)(atom_emb + ((size_t)(f * ATOM_V + a)) * EMB + c * 4);
        acc.x += v.x; acc.y += v.y; acc.z += v.z; acc.w += v.w;
    }
    *(float4*)(h + (size_t)n * EMB + c * 4) = acc;
}

// ---------------- vn broadcast init ----------------
__global__ void k_vn_init(const float* __restrict__ vn_emb, float* __restrict__ vn) {
    int idx = blockIdx.x * blockDim.x + threadIdx.x;
    if (idx >= NGRAPH * EMB) return;
    vn[idx] = vn_emb[idx % EMB];
}

// ---------------- pooled init: pooled = vn ----------------
__global__ void k_pool_init(const float* __restrict__ vn, float* __restrict__ pooled) {
    int idx = blockIdx.x * blockDim.x + threadIdx.x;
    if (idx >= NGRAPH * EMB) return;
    pooled[idx] = vn[idx];
}

// ---------------- fused: h += vn[batch]; agg = (1+eps)*h; pooled += h (opt) ----------------
__global__ void k_vnadd_agg(float* __restrict__ h, float* __restrict__ agg,
                            const float* __restrict__ vn, const int* __restrict__ batch,
                            float* __restrict__ pooled, const float* __restrict__ gin_eps,
                            int layer, int do_pool, int N) {
    int idx = blockIdx.x * blockDim.x + threadIdx.x;
    if (idx >= N * C4) return;
    int n = idx / C4, c = idx % C4;
    int b = batch[n];
    float oe = 1.f + gin_eps[layer];
    float4 hv = *(float4*)(h + (size_t)n * EMB + c * 4);
    float4 vv = *(const float4*)(vn + (size_t)b * EMB + c * 4);
    hv.x += vv.x; hv.y += vv.y; hv.z += vv.z; hv.w += vv.w;
    *(float4*)(h + (size_t)n * EMB + c * 4) = hv;
    float4 av = make_float4(hv.x * oe, hv.y * oe, hv.z * oe, hv.w * oe);
    *(float4*)(agg + (size_t)n * EMB + c * 4) = av;
    if (do_pool) {
        float* dst = pooled + (size_t)b * EMB + c * 4;
        atomicAdd(dst + 0, hv.x);
        atomicAdd(dst + 1, hv.y);
        atomicAdd(dst + 2, hv.z);
        atomicAdd(dst + 3, hv.w);
    }
}

// ---------------- edge messages: agg[col] += relu(h[row] + bond_emb(edge_attr)) ----------------
__global__ void k_edge_scatter(const float* __restrict__ h, float* __restrict__ agg,
                               const int* __restrict__ ei, const int* __restrict__ ea,
                               const float* __restrict__ bond_emb, int E) {
    int idx = blockIdx.x * blockDim.x + threadIdx.x;
    if (idx >= E * C4) return;
    int e = idx / C4, c = idx % C4;
    int row = ei[e];
    int col = ei[E + e];
    int a0 = ea[e * 3 + 0];
    int a1 = ea[e * 3 + 1];
    int a2 = ea[e * 3 + 2];
    float4 hv = *(const float4*)(h + (size_t)row * EMB + c * 4);
    float4 b0 = *(const float4*)(bond_emb + (size_t)(0 * BOND_V + a0) * EMB + c * 4);
    float4 b1 = *(const float4*)(bond_emb + (size_t)(1 * BOND_V + a1) * EMB + c * 4);
    float4 b2 = *(const float4*)(bond_emb + (size_t)(2 * BOND_V + a2) * EMB + c * 4);
    float mx = fmaxf(hv.x + b0.x + b1.x + b2.x, 0.f);
    float my = fmaxf(hv.y + b0.y + b1.y + b2.y, 0.f);
    float mz = fmaxf(hv.z + b0.z + b1.z + b2.z, 0.f);
    float mw = fmaxf(hv.w + b0.w + b1.w + b2.w, 0.f);
    float* dst = agg + (size_t)col * EMB + c * 4;
    atomicAdd(dst + 0, mx);
    atomicAdd(dst + 1, my);
    atomicAdd(dst + 2, mz);
    atomicAdd(dst + 3, mw);
}

// ---------------- SGEMM (packed f32x2 FFMA2) with fused bias + BN + optional ReLU ----------------
// out[M,Nc] = op( bn( A[M,K] @ W[K,Nc] + bias ) )
// Accumulator pairs run along M: accp[ip][j] = {row 2ip, row 2ip+1} of column j.
// A-pairs come pre-packed from SMEM via ld.shared.v2.b64; B values are broadcast-packed.
#define BM 128
#define BN 64
#define BK 16
#define TM 8
#define TN 4
__global__ __launch_bounds__(256, 2)
void k_gemm_bn(const float* __restrict__ A, const float* __restrict__ W,
               const float* __restrict__ bias,
               const float* __restrict__ bng, const float* __restrict__ bnb,
               const float* __restrict__ bnm, const float* __restrict__ bnv,
               float* __restrict__ out, int M, int K, int Nc, int do_relu) {
    __shared__ __align__(16) float As[BK][BM + 4];   // row = 528B (16B-aligned rows)
    __shared__ __align__(16) float Bs[BK][BN];       // row = 256B

    const int tid = threadIdx.x;              // 256 threads
    const int tx = tid % (BN / TN);           // 0..15
    const int ty = tid / (BN / TN);           // 0..15
    const int row0 = blockIdx.y * BM;
    const int col0 = blockIdx.x * BN;

    unsigned long long accp[TM / 2][TN];      // 16 f32x2 accumulators
#pragma unroll
    for (int ip = 0; ip < TM / 2; ip++)
#pragma unroll
        for (int j = 0; j < TN; j++) accp[ip][j] = 0ull;

    // shared-memory byte addresses for the compute loads
    const unsigned a_base =
        (unsigned)__cvta_generic_to_shared(&As[0][ty * TM]);
    const unsigned b_base =
        (unsigned)__cvta_generic_to_shared(&Bs[0][tx * TN]);

    for (int k0 = 0; k0 < K; k0 += BK) {
        // load A tile: BM x BK, stored transposed As[kk][m]
#pragma unroll
        for (int i = 0; i < (BM * BK) / 256; i++) {
            int flat = tid + i * 256;
            int m = flat / BK, kk = flat % BK;
            int gm = row0 + m, gk = k0 + kk;
            As[kk][m] = (gm < M && gk < K) ? A[(size_t)gm * K + gk] : 0.f;
        }
        // load B tile: BK x BN
#pragma unroll
        for (int i = 0; i < (BK * BN) / 256; i++) {
            int flat = tid + i * 256;
            int kk = flat / BN, n = flat % BN;
            int gk = k0 + kk, gn = col0 + n;
            Bs[kk][n] = (gk < K && gn < Nc) ? W[(size_t)gk * Nc + gn] : 0.f;
        }
        __syncthreads();

#pragma unroll
        for (int kk = 0; kk < BK; kk++) {
            // A fragment: 8 rows = 4 packed f32x2 pairs, straight from SMEM
            unsigned long long ap0, ap1, ap2, ap3;
            unsigned a_addr = a_base + kk * ((BM + 4) * 4);
            asm volatile("ld.shared.v2.b64 {%0,%1},[%2];"
                         : "=l"(ap0), "=l"(ap1) : "r"(a_addr));
            asm volatile("ld.shared.v2.b64 {%0,%1},[%2];"
                         : "=l"(ap2), "=l"(ap3) : "r"(a_addr + 16));
            // B fragment: 4 scalars, each broadcast-packed {b,b}
            float b0, b1, b2, b3;
            unsigned b_addr = b_base + kk * (BN * 4);
            asm volatile("ld.shared.v4.f32 {%0,%1,%2,%3},[%4];"
                         : "=f"(b0), "=f"(b1), "=f"(b2), "=f"(b3) : "r"(b_addr));
            unsigned long long bb0, bb1, bb2, bb3;
            asm("mov.b64 %0,{%1,%1};" : "=l"(bb0) : "f"(b0));
            asm("mov.b64 %0,{%1,%1};" : "=l"(bb1) : "f"(b1));
            asm("mov.b64 %0,{%1,%1};" : "=l"(bb2) : "f"(b2));
            asm("mov.b64 %0,{%1,%1};" : "=l"(bb3) : "f"(b3));

#define FMA2(ip, bb, j) \
            asm("fma.rn.f32x2 %0,%1,%2,%0;" : "+l"(accp[ip][j]) : "l"(ap##ip), "l"(bb))
            FMA2(0, bb0, 0); FMA2(0, bb1, 1); FMA2(0, bb2, 2); FMA2(0, bb3, 3);
            FMA2(1, bb0, 0); FMA2(1, bb1, 1); FMA2(1, bb2, 2); FMA2(1, bb3, 3);
            FMA2(2, bb0, 0); FMA2(2, bb1, 1); FMA2(2, bb2, 2); FMA2(2, bb3, 3);
            FMA2(3, bb0, 0); FMA2(3, bb1, 1); FMA2(3, bb2, 2); FMA2(3, bb3, 3);
#undef FMA2
        }
        __syncthreads();
    }

    // epilogue: bias + BN (+ ReLU)
#pragma unroll
    for (int j = 0; j < TN; j++) {
        int gn = col0 + tx * TN + j;
        if (gn >= Nc) continue;
        float s = bng[gn] * rsqrtf(bnv[gn] + BN_EPS);
        float off = bnb[gn] - bnm[gn] * s;
        float bi = bias[gn];
#pragma unroll
        for (int ip = 0; ip < TM / 2; ip++) {
            float lo, hi;
            asm("mov.b64 {%0,%1},%2;" : "=f"(lo), "=f"(hi) : "l"(accp[ip][j]));
            int gm0 = row0 + ty * TM + 2 * ip;
            if (gm0 < M) {
                float v = (lo + bi) * s + off;
                if (do_relu) v = fmaxf(v, 0.f);
                out[(size_t)gm0 * Nc + gn] = v;
            }
            if (gm0 + 1 < M) {
                float v = (hi + bi) * s + off;
                if (do_relu) v = fmaxf(v, 0.f);
                out[(size_t)(gm0 + 1) * Nc + gn] = v;
            }
        }
    }
}

// ---------------- final mean pool ----------------
__global__ void k_final_zero(float* __restrict__ out, float* __restrict__ counts) {
    int idx = blockIdx.x * blockDim.x + threadIdx.x;
    if (idx < NGRAPH * EMB) out[idx] = 0.f;
    if (idx < NGRAPH) counts[idx] = 0.f;
}
__global__ void k_final_acc(const float* __restrict__ h, const int* __restrict__ batch,
                            float* __restrict__ out, float* __restrict__ counts, int N) {
    int idx = blockIdx.x * blockDim.x + threadIdx.x;
    if (idx >= N * C4) return;
    int n = idx / C4, c = idx % C4;
    int b = batch[n];
    float4 hv = *(const float4*)(h + (size_t)n * EMB + c * 4);
    float* dst = out + (size_t)b * EMB + c * 4;
    atomicAdd(dst + 0, hv.x);
    atomicAdd(dst + 1, hv.y);
    atomicAdd(dst + 2, hv.z);
    atomicAdd(dst + 3, hv.w);
    if (c == 0) atomicAdd(counts + b, 1.f);
}
__global__ void k_final_div(float* __restrict__ out, const float* __restrict__ counts) {
    int idx = blockIdx.x * blockDim.x + threadIdx.x;
    if (idx >= NGRAPH * EMB) return;
    int g = idx / EMB;
    out[idx] /= fmaxf(counts[g], 1.f);
}

// ---------------- launch ----------------
static inline dim3 gemm_grid(int M, int Nc) {
    return dim3((Nc + BN - 1) / BN, (M + BM - 1) / BM);
}

extern "C" void kernel_launch(void* const* d_in, const int* in_sizes, int n_in,
                              void* d_out, int out_size) {
    const int*   x        = (const int*)  d_in[0];
    const int*   ei       = (const int*)  d_in[1];
    const int*   ea       = (const int*)  d_in[2];
    const int*   batch    = (const int*)  d_in[3];
    const float* atom_emb = (const float*)d_in[4];
    const float* bond_emb = (const float*)d_in[5];
    const float* vn_emb   = (const float*)d_in[6];
    const float* gin_eps  = (const float*)d_in[7];
    const float* gin_W1   = (const float*)d_in[8];
    const float* gin_b1   = (const float*)d_in[9];
    const float* gin_bn1_g= (const float*)d_in[10];
    const float* gin_bn1_b= (const float*)d_in[11];
    const float* gin_bn1_m= (const float*)d_in[12];
    const float* gin_bn1_v= (const float*)d_in[13];
    const float* gin_W2   = (const float*)d_in[14];
    const float* gin_b2   = (const float*)d_in[15];
    const float* bn_g     = (const float*)d_in[16];
    const float* bn_b     = (const float*)d_in[17];
    const float* bn_m     = (const float*)d_in[18];
    const float* bn_v     = (const float*)d_in[19];
    const float* vn_W1    = (const float*)d_in[20];
    const float* vn_b1    = (const float*)d_in[21];
    const float* vn_bn1_g = (const float*)d_in[22];
    const float* vn_bn1_b = (const float*)d_in[23];
    const float* vn_bn1_m = (const float*)d_in[24];
    const float* vn_bn1_v = (const float*)d_in[25];
    const float* vn_W2    = (const float*)d_in[26];
    const float* vn_b2    = (const float*)d_in[27];
    const float* vn_bn2_g = (const float*)d_in[28];
    const float* vn_bn2_b = (const float*)d_in[29];
    const float* vn_bn2_m = (const float*)d_in[30];
    const float* vn_bn2_v = (const float*)d_in[31];

    const int N = in_sizes[0] / ATOM_F;   // 100000
    const int E = in_sizes[1] / 2;        // 250000
    float* out = (float*)d_out;

    float *h, *agg, *t1, *vn, *pooled, *vnt, *counts;
    cudaGetSymbolAddress((void**)&h,      g_h);
    cudaGetSymbolAddress((void**)&agg,    g_agg);
    cudaGetSymbolAddress((void**)&t1,     g_t1);
    cudaGetSymbolAddress((void**)&vn,     g_vn);
    cudaGetSymbolAddress((void**)&pooled, g_pooled);
    cudaGetSymbolAddress((void**)&vnt,    g_vnt);
    cudaGetSymbolAddress((void**)&counts, g_counts);

    const int T = 256;
    const int gN  = (N * C4 + T - 1) / T;
    const int gE  = (E * C4 + T - 1) / T;
    const int gVN = (NGRAPH * EMB + T - 1) / T;

    // encode + vn init
    k_atom_encode<<<gN, T>>>(x, atom_emb, h, N);
    k_vn_init<<<gVN, T>>>(vn_emb, vn);

    for (int l = 0; l < NLAYERS; l++) {
        const int do_pool = (l < NLAYERS - 1);
        if (do_pool) k_pool_init<<<gVN, T>>>(vn, pooled);
        // h += vn[batch]; agg = (1+eps)*h; pooled += h
        k_vnadd_agg<<<gN, T>>>(h, agg, vn, batch, pooled, gin_eps, l, do_pool, N);
        // agg += scatter-add relu(h[row] + bond_emb)
        k_edge_scatter<<<gE, T>>>(h, agg, ei, ea, bond_emb, E);
        // t1 = relu(bn1(agg @ W1 + b1))  [N, 600]
        k_gemm_bn<<<gemm_grid(N, 2 * EMB), 256>>>(
            agg, gin_W1 + (size_t)l * EMB * 2 * EMB, gin_b1 + l * 2 * EMB,
            gin_bn1_g + l * 2 * EMB, gin_bn1_b + l * 2 * EMB,
            gin_bn1_m + l * 2 * EMB, gin_bn1_v + l * 2 * EMB,
            t1, N, EMB, 2 * EMB, 1);
        // h = bn(t1 @ W2 + b2) (+ relu if not last)  [N, 300]
        k_gemm_bn<<<gemm_grid(N, EMB), 256>>>(
            t1, gin_W2 + (size_t)l * 2 * EMB * EMB, gin_b2 + l * EMB,
            bn_g + l * EMB, bn_b + l * EMB, bn_m + l * EMB, bn_v + l * EMB,
            h, N, 2 * EMB, EMB, do_pool ? 1 : 0);
        if (do_pool) {
            // vn MLP
            k_gemm_bn<<<gemm_grid(NGRAPH, 2 * EMB), 256>>>(
                pooled, vn_W1 + (size_t)l * EMB * 2 * EMB, vn_b1 + l * 2 * EMB,
                vn_bn1_g + l * 2 * EMB, vn_bn1_b + l * 2 * EMB,
                vn_bn1_m + l * 2 * EMB, vn_bn1_v + l * 2 * EMB,
                vnt, NGRAPH, EMB, 2 * EMB, 1);
            k_gemm_bn<<<gemm_grid(NGRAPH, EMB), 256>>>(
                vnt, vn_W2 + (size_t)l * 2 * EMB * EMB, vn_b2 + l * EMB,
                vn_bn2_g + l * EMB, vn_bn2_b + l * EMB,
                vn_bn2_m + l * EMB, vn_bn2_v + l * EMB,
                vn, NGRAPH, 2 * EMB, EMB, 1);
        }
    }

    // global mean pool
    k_final_zero<<<gVN, T>>>(out, counts);
    k_final_acc<<<gN, T>>>(h, batch, out, counts, N);
    k_final_div<<<gVN, T>>>(out, counts);
}

// round 7
// speedup vs baseline: 1.1990x; 1.0373x over previous
#include <cuda_runtime.h>
#include <cuda_bf16.h>
#include <math.h>
#include <cstdint>

// ---------------- problem constants ----------------
#define EMB        300
#define C4         75
#define NLAYERS    5
#define NGRAPH     4096
#define ATOM_F     9
#define ATOM_V     128
#define BOND_V     8
#define BN_EPS     1e-5f
#define NMAX       100000
#define EMAX       250000
// padded K strides for MMA operands
#define KP1        320      // pad of 300
#define KP2        608      // pad of 600

// ---------------- device scratch (allocation-free; zero-initialized at load) ----------------
__device__ __align__(16) float g_h     [(size_t)NMAX * EMB];
__device__ __align__(16) float g_agg   [(size_t)NMAX * EMB];
__device__ __align__(16) float g_vn    [(size_t)NGRAPH * EMB];
__device__ __align__(16) float g_pooled[(size_t)NGRAPH * EMB];
__device__ __align__(16) float g_vnt   [(size_t)NGRAPH * 2 * EMB];
__device__            float g_counts[NGRAPH];
// bf16 hi/lo split operands (padded K strides)
__device__ __align__(16) __nv_bfloat16 g_agg_h[(size_t)NMAX * KP1];
__device__ __align__(16) __nv_bfloat16 g_agg_l[(size_t)NMAX * KP1];
__device__ __align__(16) __nv_bfloat16 g_t1_h [(size_t)NMAX * KP2];
__device__ __align__(16) __nv_bfloat16 g_t1_l [(size_t)NMAX * KP2];
// transposed+split weights: W1t [l][600][KP1], W2t [l][300][KP2]
__device__ __align__(16) __nv_bfloat16 g_w1t_h[(size_t)NLAYERS * 2 * EMB * KP1];
__device__ __align__(16) __nv_bfloat16 g_w1t_l[(size_t)NLAYERS * 2 * EMB * KP1];
__device__ __align__(16) __nv_bfloat16 g_w2t_h[(size_t)NLAYERS * EMB * KP2];
__device__ __align__(16) __nv_bfloat16 g_w2t_l[(size_t)NLAYERS * EMB * KP2];

__device__ __forceinline__ uint32_t smem_u32(const void* p) {
    uint32_t a;
    asm("{ .reg .u64 t; cvta.to.shared.u64 t, %1; cvt.u32.u64 %0, t; }" : "=r"(a) : "l"(p));
    return a;
}

#define LDSM4(r, a) asm volatile( \
    "ldmatrix.sync.aligned.m8n8.x4.shared.b16 {%0,%1,%2,%3},[%4];" \
    : "=r"((r)[0]),"=r"((r)[1]),"=r"((r)[2]),"=r"((r)[3]) : "r"(a))
#define LDSM2(r, a) asm volatile( \
    "ldmatrix.sync.aligned.m8n8.x2.shared.b16 {%0,%1},[%2];" \
    : "=r"((r)[0]),"=r"((r)[1]) : "r"(a))
#define MMA16816(c, a, b) asm volatile( \
    "mma.sync.aligned.m16n8k16.row.col.f32.bf16.bf16.f32 " \
    "{%0,%1,%2,%3},{%4,%5,%6,%7},{%8,%9},{%0,%1,%2,%3};" \
    : "+f"((c)[0]),"+f"((c)[1]),"+f"((c)[2]),"+f"((c)[3]) \
    : "r"((a)[0]),"r"((a)[1]),"r"((a)[2]),"r"((a)[3]),"r"((b)[0]),"r"((b)[1]))

// ---------------- atom encoder ----------------
__global__ void k_atom_encode(const int* __restrict__ x, const float* __restrict__ atom_emb,
                              float* __restrict__ h, int N) {
    int idx = blockIdx.x * blockDim.x + threadIdx.x;
    if (idx >= N * C4) return;
    int n = idx / C4, c = idx % C4;
    float4 acc = make_float4(0.f, 0.f, 0.f, 0.f);
#pragma unroll
    for (int f = 0; f < ATOM_F; f++) {
        int a = x[n * ATOM_F + f];
        float4 v = *(const float4*)(atom_emb + ((size_t)(f * ATOM_V + a)) * EMB + c * 4);
        acc.x += v.x; acc.y += v.y; acc.z += v.z; acc.w += v.w;
    }
    *(float4*)(h + (size_t)n * EMB + c * 4) = acc;
}

__global__ void k_vn_init(const float* __restrict__ vn_emb, float* __restrict__ vn) {
    int idx = blockIdx.x * blockDim.x + threadIdx.x;
    if (idx >= NGRAPH * EMB) return;
    vn[idx] = vn_emb[idx % EMB];
}
__global__ void k_pool_init(const float* __restrict__ vn, float* __restrict__ pooled) {
    int idx = blockIdx.x * blockDim.x + threadIdx.x;
    if (idx >= NGRAPH * EMB) return;
    pooled[idx] = vn[idx];
}

// ---------------- weight transpose + split (once per launch) ----------------
__global__ void k_prep_w(const float* __restrict__ W1, const float* __restrict__ W2,
                         __nv_bfloat16* __restrict__ w1h, __nv_bfloat16* __restrict__ w1l,
                         __nv_bfloat16* __restrict__ w2h, __nv_bfloat16* __restrict__ w2l) {
    const int SZ1 = NLAYERS * 2 * EMB * KP1;   // 960000
    const int SZ2 = NLAYERS * EMB * KP2;       // 912000
    int idx = blockIdx.x * blockDim.x + threadIdx.x;
    if (idx < SZ1) {
        int l = idx / (2 * EMB * KP1);
        int rem = idx % (2 * EMB * KP1);
        int n = rem / KP1, k = rem % KP1;
        float w = (k < EMB) ? W1[(size_t)l * EMB * 2 * EMB + (size_t)k * 2 * EMB + n] : 0.f;
        __nv_bfloat16 hi = __float2bfloat16(w);
        w1h[idx] = hi;
        w1l[idx] = __float2bfloat16(w - __bfloat162float(hi));
    } else if (idx < SZ1 + SZ2) {
        int j = idx - SZ1;
        int l = j / (EMB * KP2);
        int rem = j % (EMB * KP2);
        int n = rem / KP2, k = rem % KP2;
        float w = (k < 2 * EMB) ? W2[(size_t)l * 2 * EMB * EMB + (size_t)k * EMB + n] : 0.f;
        __nv_bfloat16 hi = __float2bfloat16(w);
        w2h[j] = hi;
        w2l[j] = __float2bfloat16(w - __bfloat162float(hi));
    }
}

// ---------------- fp32 [N,EMB] -> bf16 hi/lo [N,KP1] padded split ----------------
__global__ void k_split(const float* __restrict__ src, __nv_bfloat16* __restrict__ dh,
                        __nv_bfloat16* __restrict__ dl, int N) {
    int idx = blockIdx.x * blockDim.x + threadIdx.x;
    if (idx >= N * KP1) return;
    int n = idx / KP1, k = idx % KP1;
    float v = (k < EMB) ? src[(size_t)n * EMB + k] : 0.f;
    __nv_bfloat16 hi = __float2bfloat16(v);
    dh[idx] = hi;
    dl[idx] = __float2bfloat16(v - __bfloat162float(hi));
}

// ---------------- fused: h += vn[batch]; agg = (1+eps)*h; pooled += h ----------------
__global__ void k_vnadd_agg(float* __restrict__ h, float* __restrict__ agg,
                            const float* __restrict__ vn, const int* __restrict__ batch,
                            float* __restrict__ pooled, const float* __restrict__ gin_eps,
                            int layer, int do_pool, int N) {
    int idx = blockIdx.x * blockDim.x + threadIdx.x;
    if (idx >= N * C4) return;
    int n = idx / C4, c = idx % C4;
    int b = batch[n];
    float oe = 1.f + gin_eps[layer];
    float4 hv = *(float4*)(h + (size_t)n * EMB + c * 4);
    float4 vv = *(const float4*)(vn + (size_t)b * EMB + c * 4);
    hv.x += vv.x; hv.y += vv.y; hv.z += vv.z; hv.w += vv.w;
    *(float4*)(h + (size_t)n * EMB + c * 4) = hv;
    float4 av = make_float4(hv.x * oe, hv.y * oe, hv.z * oe, hv.w * oe);
    *(float4*)(agg + (size_t)n * EMB + c * 4) = av;
    if (do_pool) {
        float* dst = pooled + (size_t)b * EMB + c * 4;
        atomicAdd(dst + 0, hv.x);
        atomicAdd(dst + 1, hv.y);
        atomicAdd(dst + 2, hv.z);
        atomicAdd(dst + 3, hv.w);
    }
}

// ---------------- edge scatter ----------------
__global__ void k_edge_scatter(const float* __restrict__ h, float* __restrict__ agg,
                               const int* __restrict__ ei, const int* __restrict__ ea,
                               const float* __restrict__ bond_emb, int E) {
    int idx = blockIdx.x * blockDim.x + threadIdx.x;
    if (idx >= E * C4) return;
    int e = idx / C4, c = idx % C4;
    int row = ei[e];
    int col = ei[E + e];
    int a0 = ea[e * 3 + 0], a1 = ea[e * 3 + 1], a2 = ea[e * 3 + 2];
    float4 hv = *(const float4*)(h + (size_t)row * EMB + c * 4);
    float4 b0 = *(const float4*)(bond_emb + (size_t)(0 * BOND_V + a0) * EMB + c * 4);
    float4 b1 = *(const float4*)(bond_emb + (size_t)(1 * BOND_V + a1) * EMB + c * 4);
    float4 b2 = *(const float4*)(bond_emb + (size_t)(2 * BOND_V + a2) * EMB + c * 4);
    float mx = fmaxf(hv.x + b0.x + b1.x + b2.x, 0.f);
    float my = fmaxf(hv.y + b0.y + b1.y + b2.y, 0.f);
    float mz = fmaxf(hv.z + b0.z + b1.z + b2.z, 0.f);
    float mw = fmaxf(hv.w + b0.w + b1.w + b2.w, 0.f);
    float* dst = agg + (size_t)col * EMB + c * 4;
    atomicAdd(dst + 0, mx);
    atomicAdd(dst + 1, my);
    atomicAdd(dst + 2, mz);
    atomicAdd(dst + 3, mw);
}

// ================= bf16-split tensor-core GEMM (mma.sync) =================
// D[M,Nc] = A[M,K] @ W[K,Nc]; A hi/lo bf16 [M,Kpad], B hi/lo bf16 [Nc,Kpad] (W^T).
// 3 combos hi*hi + hi*lo + lo*hi accumulate into fp32.
// mode 0: write fp32 bn(+relu) to out_f32 (stride Nc).
// mode 1: write bf16 hi/lo split of bn+relu to out_hi/out_lo (stride ldo, pads zeroed).
#define MM_BM 128
#define MM_BN 64
#define MM_BK 32
#define ASTR  40   // smem row stride in bf16 (80B): conflict-free ldmatrix

__global__ __launch_bounds__(256, 2)
void k_mma_gemm(const __nv_bfloat16* __restrict__ Ah, const __nv_bfloat16* __restrict__ Al,
                const __nv_bfloat16* __restrict__ Bh, const __nv_bfloat16* __restrict__ Bl,
                const float* __restrict__ bias,
                const float* __restrict__ bng, const float* __restrict__ bnb,
                const float* __restrict__ bnm, const float* __restrict__ bnv,
                float* __restrict__ out_f32,
                __nv_bfloat16* __restrict__ out_hi, __nv_bfloat16* __restrict__ out_lo,
                int M, int Kpad, int Nc, int ldo, int do_relu, int mode) {
    __shared__ __align__(16) __nv_bfloat16 sAh[MM_BM * ASTR];
    __shared__ __align__(16) __nv_bfloat16 sAl[MM_BM * ASTR];
    __shared__ __align__(16) __nv_bfloat16 sBh[MM_BN * ASTR];
    __shared__ __align__(16) __nv_bfloat16 sBl[MM_BN * ASTR];
    __shared__ float scp[MM_BN], ofp[MM_BN];

    const int tid = threadIdx.x;
    const int lane = tid & 31;
    const int warp = tid >> 5;
    const int warp_m = warp & 3;      // 0..3 -> m offset *32
    const int warp_n = warp >> 2;     // 0..1 -> n offset *32
    const int row0 = blockIdx.y * MM_BM;
    const int col0 = blockIdx.x * MM_BN;

    // per-column epilogue constants (zero for pad columns -> auto-zero pads)
    if (tid < MM_BN) {
        int gn = col0 + tid;
        float s = 0.f, o = 0.f;
        if (gn < Nc) {
            s = bng[gn] * rsqrtf(bnv[gn] + BN_EPS);
            o = bias[gn] * s + bnb[gn] - bnm[gn] * s;
        }
        scp[tid] = s;
        ofp[tid] = o;
    }

    float acc[2][4][4];
#pragma unroll
    for (int mi = 0; mi < 2; mi++)
#pragma unroll
        for (int ni = 0; ni < 4; ni++)
#pragma unroll
            for (int q = 0; q < 4; q++) acc[mi][ni][q] = 0.f;

    const uint32_t sah = smem_u32(sAh), sal = smem_u32(sAl);
    const uint32_t sbh = smem_u32(sBh), sbl = smem_u32(sBl);
    // ldmatrix lane addressing (bytes)
    const uint32_t aoff = ((warp_m * 32 + (lane & 15)) * ASTR + (lane >> 4) * 8) * 2;
    const uint32_t boff = ((warp_n * 32 + (lane & 7)) * ASTR + ((lane >> 3) & 1) * 8) * 2;

    const uint4 z4 = make_uint4(0u, 0u, 0u, 0u);

    const int nk = Kpad / MM_BK;
    for (int ch = 0; ch < nk; ch++) {
        const int k0 = ch * MM_BK;
        // ---- A hi/lo: 128 rows x 32 bf16; 4 x uint4 (8 bf16) per row; 512 stores ----
#pragma unroll
        for (int i = 0; i < 2; i++) {
            int flat = tid + i * 256;
            int r = flat >> 2, seg = flat & 3;
            int gm = row0 + r, gk = k0 + seg * 8;
            uint4 vh = z4, vl = z4;
            if (gm < M) {
                vh = *(const uint4*)(Ah + (size_t)gm * Kpad + gk);
                vl = *(const uint4*)(Al + (size_t)gm * Kpad + gk);
            }
            *(uint4*)((char*)sAh + r * (ASTR * 2) + seg * 16) = vh;
            *(uint4*)((char*)sAl + r * (ASTR * 2) + seg * 16) = vl;
        }
        // ---- B hi/lo: 64 rows x 32 bf16; 4 x uint4 per row; 256 stores ----
        {
            int r = tid >> 2, seg = tid & 3;
            int gn = col0 + r, gk = k0 + seg * 8;
            uint4 vh = z4, vl = z4;
            if (gn < Nc) {
                vh = *(const uint4*)(Bh + (size_t)gn * Kpad + gk);
                vl = *(const uint4*)(Bl + (size_t)gn * Kpad + gk);
            }
            *(uint4*)((char*)sBh + r * (ASTR * 2) + seg * 16) = vh;
            *(uint4*)((char*)sBl + r * (ASTR * 2) + seg * 16) = vl;
        }
        __syncthreads();

#pragma unroll
        for (int ks = 0; ks < 2; ks++) {
            const uint32_t ka = ks * 32;   // 16 bf16 = 32 bytes
            uint32_t ah0[4], ah1[4], al0[4], al1[4];
            LDSM4(ah0, sah + aoff + ka);
            LDSM4(ah1, sah + aoff + 16 * ASTR * 2 + ka);
            LDSM4(al0, sal + aoff + ka);
            LDSM4(al1, sal + aoff + 16 * ASTR * 2 + ka);
            uint32_t bhf[4][2], blf[4][2];
#pragma unroll
            for (int ni = 0; ni < 4; ni++) {
                LDSM2(bhf[ni], sbh + boff + ni * 8 * ASTR * 2 + ka);
                LDSM2(blf[ni], sbl + boff + ni * 8 * ASTR * 2 + ka);
            }
#pragma unroll
            for (int ni = 0; ni < 4; ni++) {
                MMA16816(acc[0][ni], ah0, bhf[ni]);
                MMA16816(acc[1][ni], ah1, bhf[ni]);
                MMA16816(acc[0][ni], ah0, blf[ni]);
                MMA16816(acc[1][ni], ah1, blf[ni]);
                MMA16816(acc[0][ni], al0, bhf[ni]);
                MMA16816(acc[1][ni], al1, bhf[ni]);
            }
        }
        __syncthreads();
    }

    // ---- epilogue ----
    const int tg = lane >> 2;          // row-in-8
    const int np = (lane & 3) * 2;     // n pair offset
#pragma unroll
    for (int mi = 0; mi < 2; mi++) {
        int rb = row0 + warp_m * 32 + mi * 16 + tg;
#pragma unroll
        for (int ni = 0; ni < 4; ni++) {
            int ci = warp_n * 32 + ni * 8 + np;   // 0..63
            int gn = col0 + ci;
            float s0 = scp[ci], s1 = scp[ci + 1];
            float o0 = ofp[ci], o1 = ofp[ci + 1];
#pragma unroll
            for (int hb = 0; hb < 2; hb++) {
                int r = rb + hb * 8;
                if (r >= M) continue;
                float v0 = acc[mi][ni][hb * 2 + 0] * s0 + o0;
                float v1 = acc[mi][ni][hb * 2 + 1] * s1 + o1;
                if (do_relu) { v0 = fmaxf(v0, 0.f); v1 = fmaxf(v1, 0.f); }
                if (mode == 0) {
                    if (gn < Nc) {
                        float2 fv; fv.x = v0; fv.y = v1;
                        *(float2*)(out_f32 + (size_t)r * Nc + gn) = fv;
                    }
                } else {
                    if (gn < ldo) {   // pads (>=Nc) auto-zero via s=o=0
                        __nv_bfloat16 h0 = __float2bfloat16(v0);
                        __nv_bfloat16 h1 = __float2bfloat16(v1);
                        __nv_bfloat162 hp; hp.x = h0; hp.y = h1;
                        __nv_bfloat162 lp;
                        lp.x = __float2bfloat16(v0 - __bfloat162float(h0));
                        lp.y = __float2bfloat16(v1 - __bfloat162float(h1));
                        *(__nv_bfloat162*)(out_hi + (size_t)r * ldo + gn) = hp;
                        *(__nv_bfloat162*)(out_lo + (size_t)r * ldo + gn) = lp;
                    }
                }
            }
        }
    }
}

// ---------------- scalar FFMA2 SGEMM (small vn MLPs) ----------------
#define BM 128
#define BN 64
#define BK 16
#define TM 8
#define TN 4
__global__ __launch_bounds__(256, 2)
void k_gemm_bn(const float* __restrict__ A, const float* __restrict__ W,
               const float* __restrict__ bias,
               const float* __restrict__ bng, const float* __restrict__ bnb,
               const float* __restrict__ bnm, const float* __restrict__ bnv,
               float* __restrict__ out, int M, int K, int Nc, int do_relu) {
    __shared__ __align__(16) float As[BK][BM + 4];
    __shared__ __align__(16) float Bs[BK][BN];
    const int tid = threadIdx.x;
    const int tx = tid % (BN / TN);
    const int ty = tid / (BN / TN);
    const int row0 = blockIdx.y * BM;
    const int col0 = blockIdx.x * BN;
    unsigned long long accp[TM / 2][TN];
#pragma unroll
    for (int ip = 0; ip < TM / 2; ip++)
#pragma unroll
        for (int j = 0; j < TN; j++) accp[ip][j] = 0ull;
    const unsigned a_base = (unsigned)__cvta_generic_to_shared(&As[0][ty * TM]);
    const unsigned b_base = (unsigned)__cvta_generic_to_shared(&Bs[0][tx * TN]);
    for (int k0 = 0; k0 < K; k0 += BK) {
#pragma unroll
        for (int i = 0; i < (BM * BK) / 256; i++) {
            int flat = tid + i * 256;
            int m = flat / BK, kk = flat % BK;
            int gm = row0 + m, gk = k0 + kk;
            As[kk][m] = (gm < M && gk < K) ? A[(size_t)gm * K + gk] : 0.f;
        }
#pragma unroll
        for (int i = 0; i < (BK * BN) / 256; i++) {
            int flat = tid + i * 256;
            int kk = flat / BN, n = flat % BN;
            int gk = k0 + kk, gn = col0 + n;
            Bs[kk][n] = (gk < K && gn < Nc) ? W[(size_t)gk * Nc + gn] : 0.f;
        }
        __syncthreads();
#pragma unroll
        for (int kk = 0; kk < BK; kk++) {
            unsigned long long ap0, ap1, ap2, ap3;
            unsigned a_addr = a_base + kk * ((BM + 4) * 4);
            asm volatile("ld.shared.v2.b64 {%0,%1},[%2];" : "=l"(ap0), "=l"(ap1) : "r"(a_addr));
            asm volatile("ld.shared.v2.b64 {%0,%1},[%2];" : "=l"(ap2), "=l"(ap3) : "r"(a_addr + 16));
            float b0, b1, b2, b3;
            unsigned b_addr = b_base + kk * (BN * 4);
            asm volatile("ld.shared.v4.f32 {%0,%1,%2,%3},[%4];"
                         : "=f"(b0), "=f"(b1), "=f"(b2), "=f"(b3) : "r"(b_addr));
            unsigned long long bb0, bb1, bb2, bb3;
            asm("mov.b64 %0,{%1,%1};" : "=l"(bb0) : "f"(b0));
            asm("mov.b64 %0,{%1,%1};" : "=l"(bb1) : "f"(b1));
            asm("mov.b64 %0,{%1,%1};" : "=l"(bb2) : "f"(b2));
            asm("mov.b64 %0,{%1,%1};" : "=l"(bb3) : "f"(b3));
#define FMA2(ip, bb, j) \
            asm("fma.rn.f32x2 %0,%1,%2,%0;" : "+l"(accp[ip][j]) : "l"(ap##ip), "l"(bb))
            FMA2(0, bb0, 0); FMA2(0, bb1, 1); FMA2(0, bb2, 2); FMA2(0, bb3, 3);
            FMA2(1, bb0, 0); FMA2(1, bb1, 1); FMA2(1, bb2, 2); FMA2(1, bb3, 3);
            FMA2(2, bb0, 0); FMA2(2, bb1, 1); FMA2(2, bb2, 2); FMA2(2, bb3, 3);
            FMA2(3, bb0, 0); FMA2(3, bb1, 1); FMA2(3, bb2, 2); FMA2(3, bb3, 3);
#undef FMA2
        }
        __syncthreads();
    }
#pragma unroll
    for (int j = 0; j < TN; j++) {
        int gn = col0 + tx * TN + j;
        if (gn >= Nc) continue;
        float s = bng[gn] * rsqrtf(bnv[gn] + BN_EPS);
        float off = bnb[gn] - bnm[gn] * s;
        float bi = bias[gn];
#pragma unroll
        for (int ip = 0; ip < TM / 2; ip++) {
            float lo, hi;
            asm("mov.b64 {%0,%1},%2;" : "=f"(lo), "=f"(hi) : "l"(accp[ip][j]));
            int gm0 = row0 + ty * TM + 2 * ip;
            if (gm0 < M) {
                float v = (lo + bi) * s + off;
                if (do_relu) v = fmaxf(v, 0.f);
                out[(size_t)gm0 * Nc + gn] = v;
            }
            if (gm0 + 1 < M) {
                float v = (hi + bi) * s + off;
                if (do_relu) v = fmaxf(v, 0.f);
                out[(size_t)(gm0 + 1) * Nc + gn] = v;
            }
        }
    }
}

// ---------------- final mean pool ----------------
__global__ void k_final_zero(float* __restrict__ out, float* __restrict__ counts) {
    int idx = blockIdx.x * blockDim.x + threadIdx.x;
    if (idx < NGRAPH * EMB) out[idx] = 0.f;
    if (idx < NGRAPH) counts[idx] = 0.f;
}
__global__ void k_final_acc(const float* __restrict__ h, const int* __restrict__ batch,
                            float* __restrict__ out, float* __restrict__ counts, int N) {
    int idx = blockIdx.x * blockDim.x + threadIdx.x;
    if (idx >= N * C4) return;
    int n = idx / C4, c = idx % C4;
    int b = batch[n];
    float4 hv = *(const float4*)(h + (size_t)n * EMB + c * 4);
    float* dst = out + (size_t)b * EMB + c * 4;
    atomicAdd(dst + 0, hv.x);
    atomicAdd(dst + 1, hv.y);
    atomicAdd(dst + 2, hv.z);
    atomicAdd(dst + 3, hv.w);
    if (c == 0) atomicAdd(counts + b, 1.f);
}
__global__ void k_final_div(float* __restrict__ out, const float* __restrict__ counts) {
    int idx = blockIdx.x * blockDim.x + threadIdx.x;
    if (idx >= NGRAPH * EMB) return;
    int g = idx / EMB;
    out[idx] /= fmaxf(counts[g], 1.f);
}

static inline dim3 gemm_grid(int M, int Nc) {
    return dim3((Nc + BN - 1) / BN, (M + BM - 1) / BM);
}
static inline dim3 mma_grid(int M, int Nc) {
    return dim3((Nc + MM_BN - 1) / MM_BN, (M + MM_BM - 1) / MM_BM);
}

extern "C" void kernel_launch(void* const* d_in, const int* in_sizes, int n_in,
                              void* d_out, int out_size) {
    const int*   x        = (const int*)  d_in[0];
    const int*   ei       = (const int*)  d_in[1];
    const int*   ea       = (const int*)  d_in[2];
    const int*   batch    = (const int*)  d_in[3];
    const float* atom_emb = (const float*)d_in[4];
    const float* bond_emb = (const float*)d_in[5];
    const float* vn_emb   = (const float*)d_in[6];
    const float* gin_eps  = (const float*)d_in[7];
    const float* gin_W1   = (const float*)d_in[8];
    const float* gin_b1   = (const float*)d_in[9];
    const float* gin_bn1_g= (const float*)d_in[10];
    const float* gin_bn1_b= (const float*)d_in[11];
    const float* gin_bn1_m= (const float*)d_in[12];
    const float* gin_bn1_v= (const float*)d_in[13];
    const float* gin_W2   = (const float*)d_in[14];
    const float* gin_b2   = (const float*)d_in[15];
    const float* bn_g     = (const float*)d_in[16];
    const float* bn_b     = (const float*)d_in[17];
    const float* bn_m     = (const float*)d_in[18];
    const float* bn_v     = (const float*)d_in[19];
    const float* vn_W1    = (const float*)d_in[20];
    const float* vn_b1    = (const float*)d_in[21];
    const float* vn_bn1_g = (const float*)d_in[22];
    const float* vn_bn1_b = (const float*)d_in[23];
    const float* vn_bn1_m = (const float*)d_in[24];
    const float* vn_bn1_v = (const float*)d_in[25];
    const float* vn_W2    = (const float*)d_in[26];
    const float* vn_b2    = (const float*)d_in[27];
    const float* vn_bn2_g = (const float*)d_in[28];
    const float* vn_bn2_b = (const float*)d_in[29];
    const float* vn_bn2_m = (const float*)d_in[30];
    const float* vn_bn2_v = (const float*)d_in[31];

    const int N = in_sizes[0] / ATOM_F;
    const int E = in_sizes[1] / 2;
    float* out = (float*)d_out;

    float *h, *agg, *vn, *pooled, *vnt, *counts;
    __nv_bfloat16 *aggh, *aggl, *t1h, *t1l, *w1h, *w1l, *w2h, *w2l;
    cudaGetSymbolAddress((void**)&h,      g_h);
    cudaGetSymbolAddress((void**)&agg,    g_agg);
    cudaGetSymbolAddress((void**)&vn,     g_vn);
    cudaGetSymbolAddress((void**)&pooled, g_pooled);
    cudaGetSymbolAddress((void**)&vnt,    g_vnt);
    cudaGetSymbolAddress((void**)&counts, g_counts);
    cudaGetSymbolAddress((void**)&aggh,   g_agg_h);
    cudaGetSymbolAddress((void**)&aggl,   g_agg_l);
    cudaGetSymbolAddress((void**)&t1h,    g_t1_h);
    cudaGetSymbolAddress((void**)&t1l,    g_t1_l);
    cudaGetSymbolAddress((void**)&w1h,    g_w1t_h);
    cudaGetSymbolAddress((void**)&w1l,    g_w1t_l);
    cudaGetSymbolAddress((void**)&w2h,    g_w2t_h);
    cudaGetSymbolAddress((void**)&w2l,    g_w2t_l);

    const int T = 256;
    const int gN  = (N * C4 + T - 1) / T;
    const int gE  = (E * C4 + T - 1) / T;
    const int gVN = (NGRAPH * EMB + T - 1) / T;
    const int WTOT = NLAYERS * 2 * EMB * KP1 + NLAYERS * EMB * KP2;

    // prep: encode, vn init, weight transpose+split
    k_atom_encode<<<gN, T>>>(x, atom_emb, h, N);
    k_vn_init<<<gVN, T>>>(vn_emb, vn);
    k_prep_w<<<(WTOT + T - 1) / T, T>>>(gin_W1, gin_W2, w1h, w1l, w2h, w2l);

    for (int l = 0; l < NLAYERS; l++) {
        const int do_pool = (l < NLAYERS - 1);
        if (do_pool) k_pool_init<<<gVN, T>>>(vn, pooled);
        k_vnadd_agg<<<gN, T>>>(h, agg, vn, batch, pooled, gin_eps, l, do_pool, N);
        k_edge_scatter<<<gE, T>>>(h, agg, ei, ea, bond_emb, E);
        // split agg -> bf16 hi/lo (padded K=320)
        k_split<<<(N * KP1 + T - 1) / T, T>>>(agg, aggh, aggl, N);
        // GEMM1: t1(hi/lo, ld=608) = relu(bn1(agg @ W1 + b1))  [N, 600]
        k_mma_gemm<<<mma_grid(N, 2 * EMB), 256>>>(
            aggh, aggl, w1h + (size_t)l * 2 * EMB * KP1, w1l + (size_t)l * 2 * EMB * KP1,
            gin_b1 + l * 2 * EMB,
            gin_bn1_g + l * 2 * EMB, gin_bn1_b + l * 2 * EMB,
            gin_bn1_m + l * 2 * EMB, gin_bn1_v + l * 2 * EMB,
            nullptr, t1h, t1l, N, KP1, 2 * EMB, KP2, 1, 1);
        // GEMM2: h = bn(t1 @ W2 + b2) (+relu if not last)  [N, 300]
        k_mma_gemm<<<mma_grid(N, EMB), 256>>>(
            t1h, t1l, w2h + (size_t)l * EMB * KP2, w2l + (size_t)l * EMB * KP2,
            gin_b2 + l * EMB,
            bn_g + l * EMB, bn_b + l * EMB, bn_m + l * EMB, bn_v + l * EMB,
            h, nullptr, nullptr, N, KP2, EMB, EMB, do_pool ? 1 : 0, 0);
        if (do_pool) {
            k_gemm_bn<<<gemm_grid(NGRAPH, 2 * EMB), 256>>>(
                pooled, vn_W1 + (size_t)l * EMB * 2 * EMB, vn_b1 + l * 2 * EMB,
                vn_bn1_g + l * 2 * EMB, vn_bn1_b + l * 2 * EMB,
                vn_bn1_m + l * 2 * EMB, vn_bn1_v + l * 2 * EMB,
                vnt, NGRAPH, EMB, 2 * EMB, 1);
            k_gemm_bn<<<gemm_grid(NGRAPH, EMB), 256>>>(
                vnt, vn_W2 + (size_t)l * 2 * EMB * EMB, vn_b2 + l * EMB,
                vn_bn2_g + l * EMB, vn_bn2_b + l * EMB,
                vn_bn2_m + l * EMB, vn_bn2_v + l * EMB,
                vn, NGRAPH, 2 * EMB, EMB, 1);
        }
    }

    k_final_zero<<<gVN, T>>>(out, counts);
    k_final_acc<<<gN, T>>>(h, batch, out, counts, N);
    k_final_div<<<gVN, T>>>(out, counts);
}

// round 8
// speedup vs baseline: 2.0186x; 1.6836x over previous
#include <cuda_runtime.h>
#include <cuda_bf16.h>
#include <math.h>
#include <cstdint>

// ---------------- problem constants ----------------
#define EMB        300
#define C4         75
#define NLAYERS    5
#define NGRAPH     4096
#define ATOM_F     9
#define ATOM_V     128
#define BOND_V     8
#define BN_EPS     1e-5f
#define NMAX       100000
#define EMAX       250000
#define KP1        320
#define KP2        608

// ---------------- device scratch ----------------
__device__ __align__(16) float g_h     [(size_t)NMAX * EMB];
__device__ __align__(16) float g_agg   [(size_t)NMAX * EMB];
__device__ __align__(16) float g_vn    [(size_t)NGRAPH * EMB];
__device__ __align__(16) float g_pooled[(size_t)NGRAPH * EMB];
__device__ __align__(16) float g_vnt   [(size_t)NGRAPH * 2 * EMB];
__device__            float g_counts[NGRAPH];
__device__ __align__(16) __nv_bfloat16 g_agg_h[(size_t)NMAX * KP1];
__device__ __align__(16) __nv_bfloat16 g_agg_l[(size_t)NMAX * KP1];
__device__ __align__(16) __nv_bfloat16 g_t1_h [(size_t)NMAX * KP2];
__device__ __align__(16) __nv_bfloat16 g_t1_l [(size_t)NMAX * KP2];
__device__ __align__(16) __nv_bfloat16 g_w1t_h[(size_t)NLAYERS * 2 * EMB * KP1];
__device__ __align__(16) __nv_bfloat16 g_w1t_l[(size_t)NLAYERS * 2 * EMB * KP1];
__device__ __align__(16) __nv_bfloat16 g_w2t_h[(size_t)NLAYERS * EMB * KP2];
__device__ __align__(16) __nv_bfloat16 g_w2t_l[(size_t)NLAYERS * EMB * KP2];

__device__ __forceinline__ uint32_t smem_u32(const void* p) {
    uint32_t a;
    asm("{ .reg .u64 t; cvta.to.shared.u64 t, %1; cvt.u32.u64 %0, t; }" : "=r"(a) : "l"(p));
    return a;
}

#define LDSM4(r, a) asm volatile( \
    "ldmatrix.sync.aligned.m8n8.x4.shared.b16 {%0,%1,%2,%3},[%4];" \
    : "=r"((r)[0]),"=r"((r)[1]),"=r"((r)[2]),"=r"((r)[3]) : "r"(a))
#define MMA16816(c, a, b) asm volatile( \
    "mma.sync.aligned.m16n8k16.row.col.f32.bf16.bf16.f32 " \
    "{%0,%1,%2,%3},{%4,%5,%6,%7},{%8,%9},{%0,%1,%2,%3};" \
    : "+f"((c)[0]),"+f"((c)[1]),"+f"((c)[2]),"+f"((c)[3]) \
    : "r"((a)[0]),"r"((a)[1]),"r"((a)[2]),"r"((a)[3]),"r"((b)[0]),"r"((b)[1]))
#define CP_ASYNC16(saddr, gptr, ssz) asm volatile( \
    "cp.async.cg.shared.global [%0], [%1], 16, %2;" \
    :: "r"(saddr), "l"(gptr), "r"(ssz))
#define CP_COMMIT() asm volatile("cp.async.commit_group;" ::: "memory")
#define CP_WAIT1()  asm volatile("cp.async.wait_group 1;" ::: "memory")
#define CP_WAIT0()  asm volatile("cp.async.wait_group 0;" ::: "memory")

// ---------------- atom encoder ----------------
__global__ void k_atom_encode(const int* __restrict__ x, const float* __restrict__ atom_emb,
                              float* __restrict__ h, int N) {
    int idx = blockIdx.x * blockDim.x + threadIdx.x;
    if (idx >= N * C4) return;
    int n = idx / C4, c = idx % C4;
    float4 acc = make_float4(0.f, 0.f, 0.f, 0.f);
#pragma unroll
    for (int f = 0; f < ATOM_F; f++) {
        int a = x[n * ATOM_F + f];
        float4 v = *(const float4*)(atom_emb + ((size_t)(f * ATOM_V + a)) * EMB + c * 4);
        acc.x += v.x; acc.y += v.y; acc.z += v.z; acc.w += v.w;
    }
    *(float4*)(h + (size_t)n * EMB + c * 4) = acc;
}

__global__ void k_vn_init(const float* __restrict__ vn_emb, float* __restrict__ vn) {
    int idx = blockIdx.x * blockDim.x + threadIdx.x;
    if (idx >= NGRAPH * EMB) return;
    vn[idx] = vn_emb[idx % EMB];
}
__global__ void k_pool_init(const float* __restrict__ vn, float* __restrict__ pooled) {
    int idx = blockIdx.x * blockDim.x + threadIdx.x;
    if (idx >= NGRAPH * EMB) return;
    pooled[idx] = vn[idx];
}

// ---------------- weight transpose + split ----------------
__global__ void k_prep_w(const float* __restrict__ W1, const float* __restrict__ W2,
                         __nv_bfloat16* __restrict__ w1h, __nv_bfloat16* __restrict__ w1l,
                         __nv_bfloat16* __restrict__ w2h, __nv_bfloat16* __restrict__ w2l) {
    const int SZ1 = NLAYERS * 2 * EMB * KP1;
    const int SZ2 = NLAYERS * EMB * KP2;
    int idx = blockIdx.x * blockDim.x + threadIdx.x;
    if (idx < SZ1) {
        int l = idx / (2 * EMB * KP1);
        int rem = idx % (2 * EMB * KP1);
        int n = rem / KP1, k = rem % KP1;
        float w = (k < EMB) ? W1[(size_t)l * EMB * 2 * EMB + (size_t)k * 2 * EMB + n] : 0.f;
        __nv_bfloat16 hi = __float2bfloat16(w);
        w1h[idx] = hi;
        w1l[idx] = __float2bfloat16(w - __bfloat162float(hi));
    } else if (idx < SZ1 + SZ2) {
        int j = idx - SZ1;
        int l = j / (EMB * KP2);
        int rem = j % (EMB * KP2);
        int n = rem / KP2, k = rem % KP2;
        float w = (k < 2 * EMB) ? W2[(size_t)l * 2 * EMB * EMB + (size_t)k * EMB + n] : 0.f;
        __nv_bfloat16 hi = __float2bfloat16(w);
        w2h[j] = hi;
        w2l[j] = __float2bfloat16(w - __bfloat162float(hi));
    }
}

// ---------------- fp32 [N,EMB] -> bf16 hi/lo [N,KP1] ----------------
__global__ void k_split(const float* __restrict__ src, __nv_bfloat16* __restrict__ dh,
                        __nv_bfloat16* __restrict__ dl, int N) {
    int idx = blockIdx.x * blockDim.x + threadIdx.x;
    if (idx >= N * KP1) return;
    int n = idx / KP1, k = idx % KP1;
    float v = (k < EMB) ? src[(size_t)n * EMB + k] : 0.f;
    __nv_bfloat16 hi = __float2bfloat16(v);
    dh[idx] = hi;
    dl[idx] = __float2bfloat16(v - __bfloat162float(hi));
}

// ---------------- fused: h += vn[batch]; agg = (1+eps)*h; pooled += h ----------------
__global__ void k_vnadd_agg(float* __restrict__ h, float* __restrict__ agg,
                            const float* __restrict__ vn, const int* __restrict__ batch,
                            float* __restrict__ pooled, const float* __restrict__ gin_eps,
                            int layer, int do_pool, int N) {
    int idx = blockIdx.x * blockDim.x + threadIdx.x;
    if (idx >= N * C4) return;
    int n = idx / C4, c = idx % C4;
    int b = batch[n];
    float oe = 1.f + gin_eps[layer];
    float4 hv = *(float4*)(h + (size_t)n * EMB + c * 4);
    float4 vv = *(const float4*)(vn + (size_t)b * EMB + c * 4);
    hv.x += vv.x; hv.y += vv.y; hv.z += vv.z; hv.w += vv.w;
    *(float4*)(h + (size_t)n * EMB + c * 4) = hv;
    float4 av = make_float4(hv.x * oe, hv.y * oe, hv.z * oe, hv.w * oe);
    *(float4*)(agg + (size_t)n * EMB + c * 4) = av;
    if (do_pool) {
        float* dst = pooled + (size_t)b * EMB + c * 4;
        atomicAdd(dst + 0, hv.x);
        atomicAdd(dst + 1, hv.y);
        atomicAdd(dst + 2, hv.z);
        atomicAdd(dst + 3, hv.w);
    }
}

// ---------------- edge scatter ----------------
__global__ void k_edge_scatter(const float* __restrict__ h, float* __restrict__ agg,
                               const int* __restrict__ ei, const int* __restrict__ ea,
                               const float* __restrict__ bond_emb, int E) {
    int idx = blockIdx.x * blockDim.x + threadIdx.x;
    if (idx >= E * C4) return;
    int e = idx / C4, c = idx % C4;
    int row = ei[e];
    int col = ei[E + e];
    int a0 = ea[e * 3 + 0], a1 = ea[e * 3 + 1], a2 = ea[e * 3 + 2];
    float4 hv = *(const float4*)(h + (size_t)row * EMB + c * 4);
    float4 b0 = *(const float4*)(bond_emb + (size_t)(0 * BOND_V + a0) * EMB + c * 4);
    float4 b1 = *(const float4*)(bond_emb + (size_t)(1 * BOND_V + a1) * EMB + c * 4);
    float4 b2 = *(const float4*)(bond_emb + (size_t)(2 * BOND_V + a2) * EMB + c * 4);
    float mx = fmaxf(hv.x + b0.x + b1.x + b2.x, 0.f);
    float my = fmaxf(hv.y + b0.y + b1.y + b2.y, 0.f);
    float mz = fmaxf(hv.z + b0.z + b1.z + b2.z, 0.f);
    float mw = fmaxf(hv.w + b0.w + b1.w + b2.w, 0.f);
    float* dst = agg + (size_t)col * EMB + c * 4;
    atomicAdd(dst + 0, mx);
    atomicAdd(dst + 1, my);
    atomicAdd(dst + 2, mz);
    atomicAdd(dst + 3, mw);
}

// ================= bf16-split tensor-core GEMM, 128x128x32, cp.async 2-stage =================
#define MM_BM 128
#define MM_BN 128
#define MM_BK 32
#define ROWB  80                 // smem row stride bytes (40 bf16): conflict-free
#define SA_H  0
#define SA_L  10240
#define SB_H  20480
#define SB_L  30720
#define STAGE 40960
#define EPI_SC 81920
#define EPI_OF 82432
#define SMEM_TOT 82944

__global__ void __launch_bounds__(256, 2)
k_mma_gemm(const __nv_bfloat16* __restrict__ Ah, const __nv_bfloat16* __restrict__ Al,
           const __nv_bfloat16* __restrict__ Bh, const __nv_bfloat16* __restrict__ Bl,
           const float* __restrict__ bias,
           const float* __restrict__ bng, const float* __restrict__ bnb,
           const float* __restrict__ bnm, const float* __restrict__ bnv,
           float* __restrict__ out_f32,
           __nv_bfloat16* __restrict__ out_hi, __nv_bfloat16* __restrict__ out_lo,
           int M, int Kpad, int Nc, int ldo, int do_relu, int mode) {
    extern __shared__ char sm[];
    const uint32_t smb = smem_u32(sm);
    const int tid = threadIdx.x;
    const int lane = tid & 31;
    const int warp = tid >> 5;
    const int warp_m = warp & 3;      // 0..3 : 32 rows each
    const int warp_n = warp >> 2;     // 0..1 : 64 cols each
    const int row0 = blockIdx.y * MM_BM;
    const int col0 = blockIdx.x * MM_BN;

    // epilogue constants (pad cols -> s=o=0)
    float* scp = (float*)(sm + EPI_SC);
    float* ofp = (float*)(sm + EPI_OF);
    if (tid < MM_BN) {
        int gn = col0 + tid;
        float s = 0.f, o = 0.f;
        if (gn < Nc) {
            s = bng[gn] * rsqrtf(bnv[gn] + BN_EPS);
            o = bias[gn] * s + bnb[gn] - bnm[gn] * s;
        }
        scp[tid] = s;
        ofp[tid] = o;
    }

    float acc[2][8][4];
#pragma unroll
    for (int mi = 0; mi < 2; mi++)
#pragma unroll
        for (int ci = 0; ci < 8; ci++)
#pragma unroll
            for (int q = 0; q < 4; q++) acc[mi][ci][q] = 0.f;

    // staging indices: 512 x 16B per array; 2 per thread per array
    const int r0i = tid >> 2, s0i = tid & 3;
    const int r1i = (tid + 256) >> 2, s1i = (tid + 256) & 3;
    const int gmA0 = row0 + r0i, gmA1 = row0 + r1i;
    const int gnB0 = col0 + r0i, gnB1 = col0 + r1i;
    const uint32_t szA0 = (gmA0 < M) ? 16u : 0u, szA1 = (gmA1 < M) ? 16u : 0u;
    const uint32_t szB0 = (gnB0 < Nc) ? 16u : 0u, szB1 = (gnB1 < Nc) ? 16u : 0u;
    const size_t oA0 = (size_t)min(gmA0, M - 1) * Kpad + s0i * 8;
    const size_t oA1 = (size_t)min(gmA1, M - 1) * Kpad + s1i * 8;
    const size_t oB0 = (size_t)min(gnB0, Nc - 1) * Kpad + s0i * 8;
    const size_t oB1 = (size_t)min(gnB1, Nc - 1) * Kpad + s1i * 8;
    const uint32_t dA0 = r0i * ROWB + s0i * 16, dA1 = r1i * ROWB + s1i * 16;

#define ISSUE(ch, st) do { \
    const int _k0 = (ch) * MM_BK; \
    const uint32_t _sb = smb + (st) * STAGE; \
    CP_ASYNC16(_sb + SA_H + dA0, Ah + oA0 + _k0, szA0); \
    CP_ASYNC16(_sb + SA_H + dA1, Ah + oA1 + _k0, szA1); \
    CP_ASYNC16(_sb + SA_L + dA0, Al + oA0 + _k0, szA0); \
    CP_ASYNC16(_sb + SA_L + dA1, Al + oA1 + _k0, szA1); \
    CP_ASYNC16(_sb + SB_H + dA0, Bh + oB0 + _k0, szB0); \
    CP_ASYNC16(_sb + SB_H + dA1, Bh + oB1 + _k0, szB1); \
    CP_ASYNC16(_sb + SB_L + dA0, Bl + oB0 + _k0, szB0); \
    CP_ASYNC16(_sb + SB_L + dA1, Bl + oB1 + _k0, szB1); \
    CP_COMMIT(); \
} while (0)

    // ldmatrix lane addressing (bytes within array)
    const uint32_t aoff = (warp_m * 32 + (lane & 15)) * ROWB + (lane >> 4) * 16;
    const uint32_t boff = (warp_n * 64 + (lane & 7) + ((lane >> 4) << 3)) * ROWB
                        + ((lane >> 3) & 1) * 16;

    const int nk = Kpad / MM_BK;
    ISSUE(0, 0);
    for (int ch = 0; ch < nk; ch++) {
        const int st = ch & 1;
        if (ch + 1 < nk) { ISSUE(ch + 1, st ^ 1); CP_WAIT1(); }
        else             { CP_WAIT0(); }
        __syncthreads();

        const uint32_t a_h = smb + st * STAGE + SA_H;
        const uint32_t a_l = smb + st * STAGE + SA_L;
        const uint32_t b_h = smb + st * STAGE + SB_H;
        const uint32_t b_l = smb + st * STAGE + SB_L;
#pragma unroll
        for (int ks = 0; ks < 2; ks++) {
            const uint32_t ka = ks * 32;
            uint32_t ah0[4], ah1[4], al0[4], al1[4];
            LDSM4(ah0, a_h + aoff + ka);
            LDSM4(ah1, a_h + aoff + 16 * ROWB + ka);
            LDSM4(al0, a_l + aoff + ka);
            LDSM4(al1, a_l + aoff + 16 * ROWB + ka);
#pragma unroll
            for (int half = 0; half < 2; half++) {
                const int h4 = half * 4;
                uint32_t bh[2][4], bl[2][4];
                LDSM4(bh[0], b_h + boff + (half * 32 + 0) * ROWB + ka);
                LDSM4(bh[1], b_h + boff + (half * 32 + 16) * ROWB + ka);
                LDSM4(bl[0], b_l + boff + (half * 32 + 0) * ROWB + ka);
                LDSM4(bl[1], b_l + boff + (half * 32 + 16) * ROWB + ka);
#define COMBO(AF0, AF1, BF) \
                MMA16816(acc[0][h4 + 0], AF0, (BF[0] + 0)); \
                MMA16816(acc[1][h4 + 0], AF1, (BF[0] + 0)); \
                MMA16816(acc[0][h4 + 1], AF0, (BF[0] + 2)); \
                MMA16816(acc[1][h4 + 1], AF1, (BF[0] + 2)); \
                MMA16816(acc[0][h4 + 2], AF0, (BF[1] + 0)); \
                MMA16816(acc[1][h4 + 2], AF1, (BF[1] + 0)); \
                MMA16816(acc[0][h4 + 3], AF0, (BF[1] + 2)); \
                MMA16816(acc[1][h4 + 3], AF1, (BF[1] + 2));
                COMBO(ah0, ah1, bh)
                COMBO(ah0, ah1, bl)
                COMBO(al0, al1, bh)
#undef COMBO
            }
        }
        __syncthreads();
    }

    // ---- epilogue ----
    const int tg = lane >> 2;
    const int np = (lane & 3) * 2;
#pragma unroll
    for (int mi = 0; mi < 2; mi++) {
        int rb = row0 + warp_m * 32 + mi * 16 + tg;
#pragma unroll
        for (int ci8 = 0; ci8 < 8; ci8++) {
            int ci = warp_n * 64 + ci8 * 8 + np;
            int gn = col0 + ci;
            float s0 = scp[ci], s1 = scp[ci + 1];
            float o0 = ofp[ci], o1 = ofp[ci + 1];
#pragma unroll
            for (int hb = 0; hb < 2; hb++) {
                int r = rb + hb * 8;
                if (r >= M) continue;
                float v0 = acc[mi][ci8][hb * 2 + 0] * s0 + o0;
                float v1 = acc[mi][ci8][hb * 2 + 1] * s1 + o1;
                if (do_relu) { v0 = fmaxf(v0, 0.f); v1 = fmaxf(v1, 0.f); }
                if (mode == 0) {
                    if (gn < Nc) {
                        float2 fv; fv.x = v0; fv.y = v1;
                        *(float2*)(out_f32 + (size_t)r * Nc + gn) = fv;
                    }
                } else {
                    if (gn < ldo) {
                        __nv_bfloat16 h0 = __float2bfloat16(v0);
                        __nv_bfloat16 h1 = __float2bfloat16(v1);
                        __nv_bfloat162 hp; hp.x = h0; hp.y = h1;
                        __nv_bfloat162 lp;
                        lp.x = __float2bfloat16(v0 - __bfloat162float(h0));
                        lp.y = __float2bfloat16(v1 - __bfloat162float(h1));
                        *(__nv_bfloat162*)(out_hi + (size_t)r * ldo + gn) = hp;
                        *(__nv_bfloat162*)(out_lo + (size_t)r * ldo + gn) = lp;
                    }
                }
            }
        }
    }
}

// ---------------- scalar FFMA2 SGEMM (small vn MLPs) ----------------
#define BM 128
#define BN 64
#define BK 16
#define TM 8
#define TN 4
__global__ __launch_bounds__(256, 2)
void k_gemm_bn(const float* __restrict__ A, const float* __restrict__ W,
               const float* __restrict__ bias,
               const float* __restrict__ bng, const float* __restrict__ bnb,
               const float* __restrict__ bnm, const float* __restrict__ bnv,
               float* __restrict__ out, int M, int K, int Nc, int do_relu) {
    __shared__ __align__(16) float As[BK][BM + 4];
    __shared__ __align__(16) float Bs[BK][BN];
    const int tid = threadIdx.x;
    const int tx = tid % (BN / TN);
    const int ty = tid / (BN / TN);
    const int row0 = blockIdx.y * BM;
    const int col0 = blockIdx.x * BN;
    unsigned long long accp[TM / 2][TN];
#pragma unroll
    for (int ip = 0; ip < TM / 2; ip++)
#pragma unroll
        for (int j = 0; j < TN; j++) accp[ip][j] = 0ull;
    const unsigned a_base = (unsigned)__cvta_generic_to_shared(&As[0][ty * TM]);
    const unsigned b_base = (unsigned)__cvta_generic_to_shared(&Bs[0][tx * TN]);
    for (int k0 = 0; k0 < K; k0 += BK) {
#pragma unroll
        for (int i = 0; i < (BM * BK) / 256; i++) {
            int flat = tid + i * 256;
            int m = flat / BK, kk = flat % BK;
            int gm = row0 + m, gk = k0 + kk;
            As[kk][m] = (gm < M && gk < K) ? A[(size_t)gm * K + gk] : 0.f;
        }
#pragma unroll
        for (int i = 0; i < (BK * BN) / 256; i++) {
            int flat = tid + i * 256;
            int kk = flat / BN, n = flat % BN;
            int gk = k0 + kk, gn = col0 + n;
            Bs[kk][n] = (gk < K && gn < Nc) ? W[(size_t)gk * Nc + gn] : 0.f;
        }
        __syncthreads();
#pragma unroll
        for (int kk = 0; kk < BK; kk++) {
            unsigned long long ap0, ap1, ap2, ap3;
            unsigned a_addr = a_base + kk * ((BM + 4) * 4);
            asm volatile("ld.shared.v2.b64 {%0,%1},[%2];" : "=l"(ap0), "=l"(ap1) : "r"(a_addr));
            asm volatile("ld.shared.v2.b64 {%0,%1},[%2];" : "=l"(ap2), "=l"(ap3) : "r"(a_addr + 16));
            float b0, b1, b2, b3;
            unsigned b_addr = b_base + kk * (BN * 4);
            asm volatile("ld.shared.v4.f32 {%0,%1,%2,%3},[%4];"
                         : "=f"(b0), "=f"(b1), "=f"(b2), "=f"(b3) : "r"(b_addr));
            unsigned long long bb0, bb1, bb2, bb3;
            asm("mov.b64 %0,{%1,%1};" : "=l"(bb0) : "f"(b0));
            asm("mov.b64 %0,{%1,%1};" : "=l"(bb1) : "f"(b1));
            asm("mov.b64 %0,{%1,%1};" : "=l"(bb2) : "f"(b2));
            asm("mov.b64 %0,{%1,%1};" : "=l"(bb3) : "f"(b3));
#define FMA2(ip, bb, j) \
            asm("fma.rn.f32x2 %0,%1,%2,%0;" : "+l"(accp[ip][j]) : "l"(ap##ip), "l"(bb))
            FMA2(0, bb0, 0); FMA2(0, bb1, 1); FMA2(0, bb2, 2); FMA2(0, bb3, 3);
            FMA2(1, bb0, 0); FMA2(1, bb1, 1); FMA2(1, bb2, 2); FMA2(1, bb3, 3);
            FMA2(2, bb0, 0); FMA2(2, bb1, 1); FMA2(2, bb2, 2); FMA2(2, bb3, 3);
            FMA2(3, bb0, 0); FMA2(3, bb1, 1); FMA2(3, bb2, 2); FMA2(3, bb3, 3);
#undef FMA2
        }
        __syncthreads();
    }
#pragma unroll
    for (int j = 0; j < TN; j++) {
        int gn = col0 + tx * TN + j;
        if (gn >= Nc) continue;
        float s = bng[gn] * rsqrtf(bnv[gn] + BN_EPS);
        float off = bnb[gn] - bnm[gn] * s;
        float bi = bias[gn];
#pragma unroll
        for (int ip = 0; ip < TM / 2; ip++) {
            float lo, hi;
            asm("mov.b64 {%0,%1},%2;" : "=f"(lo), "=f"(hi) : "l"(accp[ip][j]));
            int gm0 = row0 + ty * TM + 2 * ip;
            if (gm0 < M) {
                float v = (lo + bi) * s + off;
                if (do_relu) v = fmaxf(v, 0.f);
                out[(size_t)gm0 * Nc + gn] = v;
            }
            if (gm0 + 1 < M) {
                float v = (hi + bi) * s + off;
                if (do_relu) v = fmaxf(v, 0.f);
                out[(size_t)(gm0 + 1) * Nc + gn] = v;
            }
        }
    }
}

// ---------------- final mean pool ----------------
__global__ void k_final_zero(float* __restrict__ out, float* __restrict__ counts) {
    int idx = blockIdx.x * blockDim.x + threadIdx.x;
    if (idx < NGRAPH * EMB) out[idx] = 0.f;
    if (idx < NGRAPH) counts[idx] = 0.f;
}
__global__ void k_final_acc(const float* __restrict__ h, const int* __restrict__ batch,
                            float* __restrict__ out, float* __restrict__ counts, int N) {
    int idx = blockIdx.x * blockDim.x + threadIdx.x;
    if (idx >= N * C4) return;
    int n = idx / C4, c = idx % C4;
    int b = batch[n];
    float4 hv = *(const float4*)(h + (size_t)n * EMB + c * 4);
    float* dst = out + (size_t)b * EMB + c * 4;
    atomicAdd(dst + 0, hv.x);
    atomicAdd(dst + 1, hv.y);
    atomicAdd(dst + 2, hv.z);
    atomicAdd(dst + 3, hv.w);
    if (c == 0) atomicAdd(counts + b, 1.f);
}
__global__ void k_final_div(float* __restrict__ out, const float* __restrict__ counts) {
    int idx = blockIdx.x * blockDim.x + threadIdx.x;
    if (idx >= NGRAPH * EMB) return;
    int g = idx / EMB;
    out[idx] /= fmaxf(counts[g], 1.f);
}

static inline dim3 gemm_grid(int M, int Nc) {
    return dim3((Nc + BN - 1) / BN, (M + BM - 1) / BM);
}
static inline dim3 mma_grid(int M, int Nc) {
    return dim3((Nc + MM_BN - 1) / MM_BN, (M + MM_BM - 1) / MM_BM);
}

extern "C" void kernel_launch(void* const* d_in, const int* in_sizes, int n_in,
                              void* d_out, int out_size) {
    const int*   x        = (const int*)  d_in[0];
    const int*   ei       = (const int*)  d_in[1];
    const int*   ea       = (const int*)  d_in[2];
    const int*   batch    = (const int*)  d_in[3];
    const float* atom_emb = (const float*)d_in[4];
    const float* bond_emb = (const float*)d_in[5];
    const float* vn_emb   = (const float*)d_in[6];
    const float* gin_eps  = (const float*)d_in[7];
    const float* gin_W1   = (const float*)d_in[8];
    const float* gin_b1   = (const float*)d_in[9];
    const float* gin_bn1_g= (const float*)d_in[10];
    const float* gin_bn1_b= (const float*)d_in[11];
    const float* gin_bn1_m= (const float*)d_in[12];
    const float* gin_bn1_v= (const float*)d_in[13];
    const float* gin_W2   = (const float*)d_in[14];
    const float* gin_b2   = (const float*)d_in[15];
    const float* bn_g     = (const float*)d_in[16];
    const float* bn_b     = (const float*)d_in[17];
    const float* bn_m     = (const float*)d_in[18];
    const float* bn_v     = (const float*)d_in[19];
    const float* vn_W1    = (const float*)d_in[20];
    const float* vn_b1    = (const float*)d_in[21];
    const float* vn_bn1_g = (const float*)d_in[22];
    const float* vn_bn1_b = (const float*)d_in[23];
    const float* vn_bn1_m = (const float*)d_in[24];
    const float* vn_bn1_v = (const float*)d_in[25];
    const float* vn_W2    = (const float*)d_in[26];
    const float* vn_b2    = (const float*)d_in[27];
    const float* vn_bn2_g = (const float*)d_in[28];
    const float* vn_bn2_b = (const float*)d_in[29];
    const float* vn_bn2_m = (const float*)d_in[30];
    const float* vn_bn2_v = (const float*)d_in[31];

    const int N = in_sizes[0] / ATOM_F;
    const int E = in_sizes[1] / 2;
    float* out = (float*)d_out;

    float *h, *agg, *vn, *pooled, *vnt, *counts;
    __nv_bfloat16 *aggh, *aggl, *t1h, *t1l, *w1h, *w1l, *w2h, *w2l;
    cudaGetSymbolAddress((void**)&h,      g_h);
    cudaGetSymbolAddress((void**)&agg,    g_agg);
    cudaGetSymbolAddress((void**)&vn,     g_vn);
    cudaGetSymbolAddress((void**)&pooled, g_pooled);
    cudaGetSymbolAddress((void**)&vnt,    g_vnt);
    cudaGetSymbolAddress((void**)&counts, g_counts);
    cudaGetSymbolAddress((void**)&aggh,   g_agg_h);
    cudaGetSymbolAddress((void**)&aggl,   g_agg_l);
    cudaGetSymbolAddress((void**)&t1h,    g_t1_h);
    cudaGetSymbolAddress((void**)&t1l,    g_t1_l);
    cudaGetSymbolAddress((void**)&w1h,    g_w1t_h);
    cudaGetSymbolAddress((void**)&w1l,    g_w1t_l);
    cudaGetSymbolAddress((void**)&w2h,    g_w2t_h);
    cudaGetSymbolAddress((void**)&w2l,    g_w2t_l);

    cudaFuncSetAttribute(k_mma_gemm, cudaFuncAttributeMaxDynamicSharedMemorySize, SMEM_TOT);

    const int T = 256;
    const int gN  = (N * C4 + T - 1) / T;
    const int gE  = (E * C4 + T - 1) / T;
    const int gVN = (NGRAPH * EMB + T - 1) / T;
    const int WTOT = NLAYERS * 2 * EMB * KP1 + NLAYERS * EMB * KP2;

    k_atom_encode<<<gN, T>>>(x, atom_emb, h, N);
    k_vn_init<<<gVN, T>>>(vn_emb, vn);
    k_prep_w<<<(WTOT + T - 1) / T, T>>>(gin_W1, gin_W2, w1h, w1l, w2h, w2l);

    for (int l = 0; l < NLAYERS; l++) {
        const int do_pool = (l < NLAYERS - 1);
        if (do_pool) k_pool_init<<<gVN, T>>>(vn, pooled);
        k_vnadd_agg<<<gN, T>>>(h, agg, vn, batch, pooled, gin_eps, l, do_pool, N);
        k_edge_scatter<<<gE, T>>>(h, agg, ei, ea, bond_emb, E);
        k_split<<<(N * KP1 + T - 1) / T, T>>>(agg, aggh, aggl, N);
        // GEMM1: t1(hi/lo, ld=608) = relu(bn1(agg @ W1 + b1))
        k_mma_gemm<<<mma_grid(N, 2 * EMB), 256, SMEM_TOT>>>(
            aggh, aggl, w1h + (size_t)l * 2 * EMB * KP1, w1l + (size_t)l * 2 * EMB * KP1,
            gin_b1 + l * 2 * EMB,
            gin_bn1_g + l * 2 * EMB, gin_bn1_b + l * 2 * EMB,
            gin_bn1_m + l * 2 * EMB, gin_bn1_v + l * 2 * EMB,
            nullptr, t1h, t1l, N, KP1, 2 * EMB, KP2, 1, 1);
        // GEMM2: h = bn(t1 @ W2 + b2) (+relu if not last)
        k_mma_gemm<<<mma_grid(N, EMB), 256, SMEM_TOT>>>(
            t1h, t1l, w2h + (size_t)l * EMB * KP2, w2l + (size_t)l * EMB * KP2,
            gin_b2 + l * EMB,
            bn_g + l * EMB, bn_b + l * EMB, bn_m + l * EMB, bn_v + l * EMB,
            h, nullptr, nullptr, N, KP2, EMB, EMB, do_pool ? 1 : 0, 0);
        if (do_pool) {
            k_gemm_bn<<<gemm_grid(NGRAPH, 2 * EMB), 256>>>(
                pooled, vn_W1 + (size_t)l * EMB * 2 * EMB, vn_b1 + l * 2 * EMB,
                vn_bn1_g + l * 2 * EMB, vn_bn1_b + l * 2 * EMB,
                vn_bn1_m + l * 2 * EMB, vn_bn1_v + l * 2 * EMB,
                vnt, NGRAPH, EMB, 2 * EMB, 1);
            k_gemm_bn<<<gemm_grid(NGRAPH, EMB), 256>>>(
                vnt, vn_W2 + (size_t)l * 2 * EMB * EMB, vn_b2 + l * EMB,
                vn_bn2_g + l * EMB, vn_bn2_b + l * EMB,
                vn_bn2_m + l * EMB, vn_bn2_v + l * EMB,
                vn, NGRAPH, 2 * EMB, EMB, 1);
        }
    }

    k_final_zero<<<gVN, T>>>(out, counts);
    k_final_acc<<<gN, T>>>(h, batch, out, counts, N);
    k_final_div<<<gVN, T>>>(out, counts);
}

// round 10
// speedup vs baseline: 2.0893x; 1.0350x over previous
#include <cuda_runtime.h>
#include <cuda_bf16.h>
#include <math.h>
#include <cstdint>

// ---------------- problem constants ----------------
#define EMB        300
#define C4         75
#define NLAYERS    5
#define NGRAPH     4096
#define ATOM_F     9
#define ATOM_V     128
#define BOND_V     8
#define BN_EPS     1e-5f
#define NMAX       100000
#define EMAX       250000
#define KP1        320
#define KP2        608

// ---------------- device scratch ----------------
__device__ __align__(16) float g_h     [(size_t)NMAX * EMB];
__device__ __align__(16) float g_agg   [(size_t)NMAX * EMB];
__device__ __align__(16) float g_vn    [(size_t)NGRAPH * EMB];
__device__ __align__(16) float g_pooled[(size_t)NGRAPH * EMB];
__device__            float g_counts[NGRAPH];
__device__ __align__(16) __nv_bfloat16 g_agg_h[(size_t)NMAX * KP1];
__device__ __align__(16) __nv_bfloat16 g_agg_l[(size_t)NMAX * KP1];
__device__ __align__(16) __nv_bfloat16 g_t1_h [(size_t)NMAX * KP2];
__device__ __align__(16) __nv_bfloat16 g_t1_l [(size_t)NMAX * KP2];
__device__ __align__(16) __nv_bfloat16 g_pl_h [(size_t)NGRAPH * KP1];
__device__ __align__(16) __nv_bfloat16 g_pl_l [(size_t)NGRAPH * KP1];
__device__ __align__(16) __nv_bfloat16 g_vnt_h[(size_t)NGRAPH * KP2];
__device__ __align__(16) __nv_bfloat16 g_vnt_l[(size_t)NGRAPH * KP2];
__device__ __align__(16) __nv_bfloat16 g_w1t_h[(size_t)NLAYERS * 2 * EMB * KP1];
__device__ __align__(16) __nv_bfloat16 g_w1t_l[(size_t)NLAYERS * 2 * EMB * KP1];
__device__ __align__(16) __nv_bfloat16 g_w2t_h[(size_t)NLAYERS * EMB * KP2];
__device__ __align__(16) __nv_bfloat16 g_w2t_l[(size_t)NLAYERS * EMB * KP2];
__device__ __align__(16) __nv_bfloat16 g_wv1_h[(size_t)(NLAYERS - 1) * 2 * EMB * KP1];
__device__ __align__(16) __nv_bfloat16 g_wv1_l[(size_t)(NLAYERS - 1) * 2 * EMB * KP1];
__device__ __align__(16) __nv_bfloat16 g_wv2_h[(size_t)(NLAYERS - 1) * EMB * KP2];
__device__ __align__(16) __nv_bfloat16 g_wv2_l[(size_t)(NLAYERS - 1) * EMB * KP2];

__device__ __forceinline__ uint32_t smem_u32(const void* p) {
    uint32_t a;
    asm("{ .reg .u64 t; cvta.to.shared.u64 t, %1; cvt.u32.u64 %0, t; }" : "=r"(a) : "l"(p));
    return a;
}

#define LDSM4(r, a) asm volatile( \
    "ldmatrix.sync.aligned.m8n8.x4.shared.b16 {%0,%1,%2,%3},[%4];" \
    : "=r"((r)[0]),"=r"((r)[1]),"=r"((r)[2]),"=r"((r)[3]) : "r"(a))
#define MMA16816(c, a, b) asm volatile( \
    "mma.sync.aligned.m16n8k16.row.col.f32.bf16.bf16.f32 " \
    "{%0,%1,%2,%3},{%4,%5,%6,%7},{%8,%9},{%0,%1,%2,%3};" \
    : "+f"((c)[0]),"+f"((c)[1]),"+f"((c)[2]),"+f"((c)[3]) \
    : "r"((a)[0]),"r"((a)[1]),"r"((a)[2]),"r"((a)[3]),"r"((b)[0]),"r"((b)[1]))
#define CP_ASYNC16(saddr, gptr, ssz) asm volatile( \
    "cp.async.cg.shared.global [%0], [%1], 16, %2;" \
    :: "r"(saddr), "l"(gptr), "r"(ssz))
#define CP_COMMIT() asm volatile("cp.async.commit_group;" ::: "memory")
#define CP_WAIT0()  asm volatile("cp.async.wait_group 0;" ::: "memory")

// ---------------- atom encoder ----------------
__global__ void k_atom_encode(const int* __restrict__ x, const float* __restrict__ atom_emb,
                              float* __restrict__ h, int N) {
    int idx = blockIdx.x * blockDim.x + threadIdx.x;
    if (idx >= N * C4) return;
    int n = idx / C4, c = idx % C4;
    float4 acc = make_float4(0.f, 0.f, 0.f, 0.f);
#pragma unroll
    for (int f = 0; f < ATOM_F; f++) {
        int a = x[n * ATOM_F + f];
        float4 v = *(const float4*)(atom_emb + ((size_t)(f * ATOM_V + a)) * EMB + c * 4);
        acc.x += v.x; acc.y += v.y; acc.z += v.z; acc.w += v.w;
    }
    *(float4*)(h + (size_t)n * EMB + c * 4) = acc;
}

// vn_init also initializes pooled (= vn)
__global__ void k_vn_init(const float* __restrict__ vn_emb, float* __restrict__ vn,
                          float* __restrict__ pooled) {
    int idx = blockIdx.x * blockDim.x + threadIdx.x;
    if (idx >= NGRAPH * EMB) return;
    float v = vn_emb[idx % EMB];
    vn[idx] = v;
    pooled[idx] = v;
}

// ---------------- weight transpose + split (gin + vn weights) ----------------
__global__ void k_prep_w(const float* __restrict__ W1, const float* __restrict__ W2,
                         const float* __restrict__ V1, const float* __restrict__ V2,
                         __nv_bfloat16* __restrict__ w1h, __nv_bfloat16* __restrict__ w1l,
                         __nv_bfloat16* __restrict__ w2h, __nv_bfloat16* __restrict__ w2l,
                         __nv_bfloat16* __restrict__ v1h, __nv_bfloat16* __restrict__ v1l,
                         __nv_bfloat16* __restrict__ v2h, __nv_bfloat16* __restrict__ v2l) {
    const int SZ1 = NLAYERS * 2 * EMB * KP1;
    const int SZ2 = NLAYERS * EMB * KP2;
    const int SZ3 = (NLAYERS - 1) * 2 * EMB * KP1;
    const int SZ4 = (NLAYERS - 1) * EMB * KP2;
    int idx = blockIdx.x * blockDim.x + threadIdx.x;
    if (idx < SZ1) {
        int l = idx / (2 * EMB * KP1);
        int rem = idx % (2 * EMB * KP1);
        int n = rem / KP1, k = rem % KP1;
        float w = (k < EMB) ? W1[(size_t)l * EMB * 2 * EMB + (size_t)k * 2 * EMB + n] : 0.f;
        __nv_bfloat16 hi = __float2bfloat16(w);
        w1h[idx] = hi;
        w1l[idx] = __float2bfloat16(w - __bfloat162float(hi));
    } else if (idx < SZ1 + SZ2) {
        int j = idx - SZ1;
        int l = j / (EMB * KP2);
        int rem = j % (EMB * KP2);
        int n = rem / KP2, k = rem % KP2;
        float w = (k < 2 * EMB) ? W2[(size_t)l * 2 * EMB * EMB + (size_t)k * EMB + n] : 0.f;
        __nv_bfloat16 hi = __float2bfloat16(w);
        w2h[j] = hi;
        w2l[j] = __float2bfloat16(w - __bfloat162float(hi));
    } else if (idx < SZ1 + SZ2 + SZ3) {
        int j = idx - SZ1 - SZ2;
        int l = j / (2 * EMB * KP1);
        int rem = j % (2 * EMB * KP1);
        int n = rem / KP1, k = rem % KP1;
        float w = (k < EMB) ? V1[(size_t)l * EMB * 2 * EMB + (size_t)k * 2 * EMB + n] : 0.f;
        __nv_bfloat16 hi = __float2bfloat16(w);
        v1h[j] = hi;
        v1l[j] = __float2bfloat16(w - __bfloat162float(hi));
    } else if (idx < SZ1 + SZ2 + SZ3 + SZ4) {
        int j = idx - SZ1 - SZ2 - SZ3;
        int l = j / (EMB * KP2);
        int rem = j % (EMB * KP2);
        int n = rem / KP2, k = rem % KP2;
        float w = (k < 2 * EMB) ? V2[(size_t)l * 2 * EMB * EMB + (size_t)k * EMB + n] : 0.f;
        __nv_bfloat16 hi = __float2bfloat16(w);
        v2h[j] = hi;
        v2l[j] = __float2bfloat16(w - __bfloat162float(hi));
    }
}

// ---------------- fp32 [N,EMB] -> bf16 hi/lo [N,KP1] ----------------
__global__ void k_split(const float* __restrict__ src, __nv_bfloat16* __restrict__ dh,
                        __nv_bfloat16* __restrict__ dl, int N) {
    int idx = blockIdx.x * blockDim.x + threadIdx.x;
    if (idx >= N * KP1) return;
    int n = idx / KP1, k = idx % KP1;
    float v = (k < EMB) ? src[(size_t)n * EMB + k] : 0.f;
    __nv_bfloat16 hi = __float2bfloat16(v);
    dh[idx] = hi;
    dl[idx] = __float2bfloat16(v - __bfloat162float(hi));
}

// ---------------- fused: h += vn[batch]; agg = (1+eps)*h; pooled += h ----------------
__global__ void k_vnadd_agg(float* __restrict__ h, float* __restrict__ agg,
                            const float* __restrict__ vn, const int* __restrict__ batch,
                            float* __restrict__ pooled, const float* __restrict__ gin_eps,
                            int layer, int do_pool, int N) {
    int idx = blockIdx.x * blockDim.x + threadIdx.x;
    if (idx >= N * C4) return;
    int n = idx / C4, c = idx % C4;
    int b = batch[n];
    float oe = 1.f + gin_eps[layer];
    float4 hv = *(float4*)(h + (size_t)n * EMB + c * 4);
    float4 vv = *(const float4*)(vn + (size_t)b * EMB + c * 4);
    hv.x += vv.x; hv.y += vv.y; hv.z += vv.z; hv.w += vv.w;
    *(float4*)(h + (size_t)n * EMB + c * 4) = hv;
    float4 av = make_float4(hv.x * oe, hv.y * oe, hv.z * oe, hv.w * oe);
    *(float4*)(agg + (size_t)n * EMB + c * 4) = av;
    if (do_pool) {
        float* dst = pooled + (size_t)b * EMB + c * 4;
        atomicAdd(dst + 0, hv.x);
        atomicAdd(dst + 1, hv.y);
        atomicAdd(dst + 2, hv.z);
        atomicAdd(dst + 3, hv.w);
    }
}

// ---------------- edge scatter ----------------
__global__ void k_edge_scatter(const float* __restrict__ h, float* __restrict__ agg,
                               const int* __restrict__ ei, const int* __restrict__ ea,
                               const float* __restrict__ bond_emb, int E) {
    int idx = blockIdx.x * blockDim.x + threadIdx.x;
    if (idx >= E * C4) return;
    int e = idx / C4, c = idx % C4;
    int row = ei[e];
    int col = ei[E + e];
    int a0 = ea[e * 3 + 0], a1 = ea[e * 3 + 1], a2 = ea[e * 3 + 2];
    float4 hv = *(const float4*)(h + (size_t)row * EMB + c * 4);
    float4 b0 = *(const float4*)(bond_emb + (size_t)(0 * BOND_V + a0) * EMB + c * 4);
    float4 b1 = *(const float4*)(bond_emb + (size_t)(1 * BOND_V + a1) * EMB + c * 4);
    float4 b2 = *(const float4*)(bond_emb + (size_t)(2 * BOND_V + a2) * EMB + c * 4);
    float mx = fmaxf(hv.x + b0.x + b1.x + b2.x, 0.f);
    float my = fmaxf(hv.y + b0.y + b1.y + b2.y, 0.f);
    float mz = fmaxf(hv.z + b0.z + b1.z + b2.z, 0.f);
    float mw = fmaxf(hv.w + b0.w + b1.w + b2.w, 0.f);
    float* dst = agg + (size_t)col * EMB + c * 4;
    atomicAdd(dst + 0, mx);
    atomicAdd(dst + 1, my);
    atomicAdd(dst + 2, mz);
    atomicAdd(dst + 3, mw);
}

// ================= bf16-split tensor-core GEMM, 128x128x32, cp.async 2-stage =================
// mode 0: fp32 bn(+relu) -> out_f32
// mode 1: bf16 hi/lo split -> out_hi/out_lo (stride ldo, pads zeroed)
// mode 2: fp32 bn(+relu) -> out_f32 AND out_f32b (vn + pooled reinit)
#define MM_BM 128
#define MM_BN 128
#define MM_BK 32
#define ROWB  80
#define SA_H  0
#define SA_L  10240
#define SB_H  20480
#define SB_L  30720
#define STAGE 40960
#define EPI_SC 81920
#define EPI_OF 82432
#define SMEM_TOT 82944

__global__ void __launch_bounds__(256, 2)
k_mma_gemm(const __nv_bfloat16* __restrict__ Ah, const __nv_bfloat16* __restrict__ Al,
           const __nv_bfloat16* __restrict__ Bh, const __nv_bfloat16* __restrict__ Bl,
           const float* __restrict__ bias,
           const float* __restrict__ bng, const float* __restrict__ bnb,
           const float* __restrict__ bnm, const float* __restrict__ bnv,
           float* __restrict__ out_f32, float* __restrict__ out_f32b,
           __nv_bfloat16* __restrict__ out_hi, __nv_bfloat16* __restrict__ out_lo,
           int M, int Kpad, int Nc, int ldo, int do_relu, int mode) {
    extern __shared__ char sm[];
    const uint32_t smb = smem_u32(sm);
    const int tid = threadIdx.x;
    const int lane = tid & 31;
    const int warp = tid >> 5;
    const int warp_m = warp & 3;
    const int warp_n = warp >> 2;
    const int row0 = blockIdx.y * MM_BM;
    const int col0 = blockIdx.x * MM_BN;

    float* scp = (float*)(sm + EPI_SC);
    float* ofp = (float*)(sm + EPI_OF);
    if (tid < MM_BN) {
        int gn = col0 + tid;
        float s = 0.f, o = 0.f;
        if (gn < Nc) {
            s = bng[gn] * rsqrtf(bnv[gn] + BN_EPS);
            o = bias[gn] * s + bnb[gn] - bnm[gn] * s;
        }
        scp[tid] = s;
        ofp[tid] = o;
    }

    float acc[2][8][4];
#pragma unroll
    for (int mi = 0; mi < 2; mi++)
#pragma unroll
        for (int ci = 0; ci < 8; ci++)
#pragma unroll
            for (int q = 0; q < 4; q++) acc[mi][ci][q] = 0.f;

    const int r0i = tid >> 2, s0i = tid & 3;
    const int r1i = (tid + 256) >> 2, s1i = (tid + 256) & 3;
    const int gmA0 = row0 + r0i, gmA1 = row0 + r1i;
    const int gnB0 = col0 + r0i, gnB1 = col0 + r1i;
    const uint32_t szA0 = (gmA0 < M) ? 16u : 0u, szA1 = (gmA1 < M) ? 16u : 0u;
    const uint32_t szB0 = (gnB0 < Nc) ? 16u : 0u, szB1 = (gnB1 < Nc) ? 16u : 0u;
    const size_t oA0 = (size_t)min(gmA0, M - 1) * Kpad + s0i * 8;
    const size_t oA1 = (size_t)min(gmA1, M - 1) * Kpad + s1i * 8;
    const size_t oB0 = (size_t)min(gnB0, Nc - 1) * Kpad + s0i * 8;
    const size_t oB1 = (size_t)min(gnB1, Nc - 1) * Kpad + s1i * 8;
    const uint32_t dA0 = r0i * ROWB + s0i * 16, dA1 = r1i * ROWB + s1i * 16;

#define ISSUE(ch, st) do { \
    const int _k0 = (ch) * MM_BK; \
    const uint32_t _sb = smb + (st) * STAGE; \
    CP_ASYNC16(_sb + SA_H + dA0, Ah + oA0 + _k0, szA0); \
    CP_ASYNC16(_sb + SA_H + dA1, Ah + oA1 + _k0, szA1); \
    CP_ASYNC16(_sb + SA_L + dA0, Al + oA0 + _k0, szA0); \
    CP_ASYNC16(_sb + SA_L + dA1, Al + oA1 + _k0, szA1); \
    CP_ASYNC16(_sb + SB_H + dA0, Bh + oB0 + _k0, szB0); \
    CP_ASYNC16(_sb + SB_H + dA1, Bh + oB1 + _k0, szB1); \
    CP_ASYNC16(_sb + SB_L + dA0, Bl + oB0 + _k0, szB0); \
    CP_ASYNC16(_sb + SB_L + dA1, Bl + oB1 + _k0, szB1); \
    CP_COMMIT(); \
} while (0)

    const uint32_t aoff = (warp_m * 32 + (lane & 15)) * ROWB + (lane >> 4) * 16;
    const uint32_t boff = (warp_n * 64 + (lane & 7) + ((lane >> 4) << 3)) * ROWB
                        + ((lane >> 3) & 1) * 16;

    const int nk = Kpad / MM_BK;
    ISSUE(0, 0);
    for (int ch = 0; ch < nk; ch++) {
        const int st = ch & 1;
        CP_WAIT0();            // ch's data resident
        __syncthreads();       // all warps done with stage st's previous contents
        if (ch + 1 < nk) ISSUE(ch + 1, st ^ 1);   // overlaps with compute below

        const uint32_t a_h = smb + st * STAGE + SA_H;
        const uint32_t a_l = smb + st * STAGE + SA_L;
        const uint32_t b_h = smb + st * STAGE + SB_H;
        const uint32_t b_l = smb + st * STAGE + SB_L;
#pragma unroll
        for (int ks = 0; ks < 2; ks++) {
            const uint32_t ka = ks * 32;
            uint32_t ah0[4], ah1[4], al0[4], al1[4];
            LDSM4(ah0, a_h + aoff + ka);
            LDSM4(ah1, a_h + aoff + 16 * ROWB + ka);
            LDSM4(al0, a_l + aoff + ka);
            LDSM4(al1, a_l + aoff + 16 * ROWB + ka);
#pragma unroll
            for (int half = 0; half < 2; half++) {
                const int h4 = half * 4;
                uint32_t bh[2][4], bl[2][4];
                LDSM4(bh[0], b_h + boff + (half * 32 + 0) * ROWB + ka);
                LDSM4(bh[1], b_h + boff + (half * 32 + 16) * ROWB + ka);
                LDSM4(bl[0], b_l + boff + (half * 32 + 0) * ROWB + ka);
                LDSM4(bl[1], b_l + boff + (half * 32 + 16) * ROWB + ka);
#define COMBO(AF0, AF1, BF) \
                MMA16816(acc[0][h4 + 0], AF0, (BF[0] + 0)); \
                MMA16816(acc[1][h4 + 0], AF1, (BF[0] + 0)); \
                MMA16816(acc[0][h4 + 1], AF0, (BF[0] + 2)); \
                MMA16816(acc[1][h4 + 1], AF1, (BF[0] + 2)); \
                MMA16816(acc[0][h4 + 2], AF0, (BF[1] + 0)); \
                MMA16816(acc[1][h4 + 2], AF1, (BF[1] + 0)); \
                MMA16816(acc[0][h4 + 3], AF0, (BF[1] + 2)); \
                MMA16816(acc[1][h4 + 3], AF1, (BF[1] + 2));
                COMBO(ah0, ah1, bh)
                COMBO(ah0, ah1, bl)
                COMBO(al0, al1, bh)
#undef COMBO
            }
        }
        __syncthreads();       // readers done before stage st is refilled (ch+2)
    }

    // ---- epilogue ----
    const int tg = lane >> 2;
    const int np = (lane & 3) * 2;
#pragma unroll
    for (int mi = 0; mi < 2; mi++) {
        int rb = row0 + warp_m * 32 + mi * 16 + tg;
#pragma unroll
        for (int ci8 = 0; ci8 < 8; ci8++) {
            int ci = warp_n * 64 + ci8 * 8 + np;
            int gn = col0 + ci;
            float s0 = scp[ci], s1 = scp[ci + 1];
            float o0 = ofp[ci], o1 = ofp[ci + 1];
#pragma unroll
            for (int hb = 0; hb < 2; hb++) {
                int r = rb + hb * 8;
                if (r >= M) continue;
                float v0 = acc[mi][ci8][hb * 2 + 0] * s0 + o0;
                float v1 = acc[mi][ci8][hb * 2 + 1] * s1 + o1;
                if (do_relu) { v0 = fmaxf(v0, 0.f); v1 = fmaxf(v1, 0.f); }
                if (mode == 1) {
                    if (gn < ldo) {
                        __nv_bfloat16 h0 = __float2bfloat16(v0);
                        __nv_bfloat16 h1 = __float2bfloat16(v1);
                        __nv_bfloat162 hp; hp.x = h0; hp.y = h1;
                        __nv_bfloat162 lp;
                        lp.x = __float2bfloat16(v0 - __bfloat162float(h0));
                        lp.y = __float2bfloat16(v1 - __bfloat162float(h1));
                        *(__nv_bfloat162*)(out_hi + (size_t)r * ldo + gn) = hp;
                        *(__nv_bfloat162*)(out_lo + (size_t)r * ldo + gn) = lp;
                    }
                } else {
                    if (gn < Nc) {
                        float2 fv; fv.x = v0; fv.y = v1;
                        *(float2*)(out_f32 + (size_t)r * Nc + gn) = fv;
                        if (mode == 2)
                            *(float2*)(out_f32b + (size_t)r * Nc + gn) = fv;
                    }
                }
            }
        }
    }
}

// ---------------- final mean pool ----------------
__global__ void k_final_zero(float* __restrict__ out, float* __restrict__ counts) {
    int idx = blockIdx.x * blockDim.x + threadIdx.x;
    if (idx < NGRAPH * EMB) out[idx] = 0.f;
    if (idx < NGRAPH) counts[idx] = 0.f;
}
__global__ void k_final_acc(const float* __restrict__ h, const int* __restrict__ batch,
                            float* __restrict__ out, float* __restrict__ counts, int N) {
    int idx = blockIdx.x * blockDim.x + threadIdx.x;
    if (idx >= N * C4) return;
    int n = idx / C4, c = idx % C4;
    int b = batch[n];
    float4 hv = *(const float4*)(h + (size_t)n * EMB + c * 4);
    float* dst = out + (size_t)b * EMB + c * 4;
    atomicAdd(dst + 0, hv.x);
    atomicAdd(dst + 1, hv.y);
    atomicAdd(dst + 2, hv.z);
    atomicAdd(dst + 3, hv.w);
    if (c == 0) atomicAdd(counts + b, 1.f);
}
__global__ void k_final_div(float* __restrict__ out, const float* __restrict__ counts) {
    int idx = blockIdx.x * blockDim.x + threadIdx.x;
    if (idx >= NGRAPH * EMB) return;
    int g = idx / EMB;
    out[idx] /= fmaxf(counts[g], 1.f);
}

static inline dim3 mma_grid(int M, int Nc) {
    return dim3((Nc + MM_BN - 1) / MM_BN, (M + MM_BM - 1) / MM_BM);
}

extern "C" void kernel_launch(void* const* d_in, const int* in_sizes, int n_in,
                              void* d_out, int out_size) {
    const int*   x        = (const int*)  d_in[0];
    const int*   ei       = (const int*)  d_in[1];
    const int*   ea       = (const int*)  d_in[2];
    const int*   batch    = (const int*)  d_in[3];
    const float* atom_emb = (const float*)d_in[4];
    const float* bond_emb = (const float*)d_in[5];
    const float* vn_emb   = (const float*)d_in[6];
    const float* gin_eps  = (const float*)d_in[7];
    const float* gin_W1   = (const float*)d_in[8];
    const float* gin_b1   = (const float*)d_in[9];
    const float* gin_bn1_g= (const float*)d_in[10];
    const float* gin_bn1_b= (const float*)d_in[11];
    const float* gin_bn1_m= (const float*)d_in[12];
    const float* gin_bn1_v= (const float*)d_in[13];
    const float* gin_W2   = (const float*)d_in[14];
    const float* gin_b2   = (const float*)d_in[15];
    const float* bn_g     = (const float*)d_in[16];
    const float* bn_b     = (const float*)d_in[17];
    const float* bn_m     = (const float*)d_in[18];
    const float* bn_v     = (const float*)d_in[19];
    const float* vn_W1    = (const float*)d_in[20];
    const float* vn_b1    = (const float*)d_in[21];
    const float* vn_bn1_g = (const float*)d_in[22];
    const float* vn_bn1_b = (const float*)d_in[23];
    const float* vn_bn1_m = (const float*)d_in[24];
    const float* vn_bn1_v = (const float*)d_in[25];
    const float* vn_W2    = (const float*)d_in[26];
    const float* vn_b2    = (const float*)d_in[27];
    const float* vn_bn2_g = (const float*)d_in[28];
    const float* vn_bn2_b = (const float*)d_in[29];
    const float* vn_bn2_m = (const float*)d_in[30];
    const float* vn_bn2_v = (const float*)d_in[31];

    const int N = in_sizes[0] / ATOM_F;
    const int E = in_sizes[1] / 2;
    float* out = (float*)d_out;

    float *h, *agg, *vn, *pooled, *counts;
    __nv_bfloat16 *aggh, *aggl, *t1h, *t1l, *plh, *pll, *vnth, *vntl;
    __nv_bfloat16 *w1h, *w1l, *w2h, *w2l, *v1h, *v1l, *v2h, *v2l;
    cudaGetSymbolAddress((void**)&h,      g_h);
    cudaGetSymbolAddress((void**)&agg,    g_agg);
    cudaGetSymbolAddress((void**)&vn,     g_vn);
    cudaGetSymbolAddress((void**)&pooled, g_pooled);
    cudaGetSymbolAddress((void**)&counts, g_counts);
    cudaGetSymbolAddress((void**)&aggh,   g_agg_h);
    cudaGetSymbolAddress((void**)&aggl,   g_agg_l);
    cudaGetSymbolAddress((void**)&t1h,    g_t1_h);
    cudaGetSymbolAddress((void**)&t1l,    g_t1_l);
    cudaGetSymbolAddress((void**)&plh,    g_pl_h);
    cudaGetSymbolAddress((void**)&pll,    g_pl_l);
    cudaGetSymbolAddress((void**)&vnth,   g_vnt_h);
    cudaGetSymbolAddress((void**)&vntl,   g_vnt_l);
    cudaGetSymbolAddress((void**)&w1h,    g_w1t_h);
    cudaGetSymbolAddress((void**)&w1l,    g_w1t_l);
    cudaGetSymbolAddress((void**)&w2h,    g_w2t_h);
    cudaGetSymbolAddress((void**)&w2l,    g_w2t_l);
    cudaGetSymbolAddress((void**)&v1h,    g_wv1_h);
    cudaGetSymbolAddress((void**)&v1l,    g_wv1_l);
    cudaGetSymbolAddress((void**)&v2h,    g_wv2_h);
    cudaGetSymbolAddress((void**)&v2l,    g_wv2_l);

    cudaFuncSetAttribute(k_mma_gemm, cudaFuncAttributeMaxDynamicSharedMemorySize, SMEM_TOT);

    const int T = 256;
    const int gN  = (N * C4 + T - 1) / T;
    const int gE  = (E * C4 + T - 1) / T;
    const int gVN = (NGRAPH * EMB + T - 1) / T;
    const int WTOT = NLAYERS * 2 * EMB * KP1 + NLAYERS * EMB * KP2
                   + (NLAYERS - 1) * 2 * EMB * KP1 + (NLAYERS - 1) * EMB * KP2;

    // launch order puts k_edge_scatter at index 3 for ncu's capture slot
    k_atom_encode<<<gN, T>>>(x, atom_emb, h, N);                       // 0
    k_vn_init<<<gVN, T>>>(vn_emb, vn, pooled);                         // 1

    for (int l = 0; l < NLAYERS; l++) {
        const int do_pool = (l < NLAYERS - 1);
        k_vnadd_agg<<<gN, T>>>(h, agg, vn, batch, pooled, gin_eps, l, do_pool, N);   // l=0: 2
        k_edge_scatter<<<gE, T>>>(h, agg, ei, ea, bond_emb, E);                      // l=0: 3
        if (l == 0)
            k_prep_w<<<(WTOT + T - 1) / T, T>>>(gin_W1, gin_W2, vn_W1, vn_W2,
                                                w1h, w1l, w2h, w2l, v1h, v1l, v2h, v2l);
        k_split<<<(N * KP1 + T - 1) / T, T>>>(agg, aggh, aggl, N);
        // GEMM1: t1(hi/lo) = relu(bn1(agg @ W1 + b1))
        k_mma_gemm<<<mma_grid(N, 2 * EMB), 256, SMEM_TOT>>>(
            aggh, aggl, w1h + (size_t)l * 2 * EMB * KP1, w1l + (size_t)l * 2 * EMB * KP1,
            gin_b1 + l * 2 * EMB,
            gin_bn1_g + l * 2 * EMB, gin_bn1_b + l * 2 * EMB,
            gin_bn1_m + l * 2 * EMB, gin_bn1_v + l * 2 * EMB,
            nullptr, nullptr, t1h, t1l, N, KP1, 2 * EMB, KP2, 1, 1);
        // GEMM2: h = bn(t1 @ W2 + b2) (+relu if not last)
        k_mma_gemm<<<mma_grid(N, EMB), 256, SMEM_TOT>>>(
            t1h, t1l, w2h + (size_t)l * EMB * KP2, w2l + (size_t)l * EMB * KP2,
            gin_b2 + l * EMB,
            bn_g + l * EMB, bn_b + l * EMB, bn_m + l * EMB, bn_v + l * EMB,
            h, nullptr, nullptr, nullptr, N, KP2, EMB, EMB, do_pool ? 1 : 0, 0);
        if (do_pool) {
            // vn MLP on tensor cores: split pooled, two GEMMs; second writes vn AND pooled
            k_split<<<(NGRAPH * KP1 + T - 1) / T, T>>>(pooled, plh, pll, NGRAPH);
            k_mma_gemm<<<mma_grid(NGRAPH, 2 * EMB), 256, SMEM_TOT>>>(
                plh, pll, v1h + (size_t)l * 2 * EMB * KP1, v1l + (size_t)l * 2 * EMB * KP1,
                vn_b1 + l * 2 * EMB,
                vn_bn1_g + l * 2 * EMB, vn_bn1_b + l * 2 * EMB,
                vn_bn1_m + l * 2 * EMB, vn_bn1_v + l * 2 * EMB,
                nullptr, nullptr, vnth, vntl, NGRAPH, KP1, 2 * EMB, KP2, 1, 1);
            k_mma_gemm<<<mma_grid(NGRAPH, EMB), 256, SMEM_TOT>>>(
                vnth, vntl, v2h + (size_t)l * EMB * KP2, v2l + (size_t)l * EMB * KP2,
                vn_b2 + l * EMB,
                vn_bn2_g + l * EMB, vn_bn2_b + l * EMB,
                vn_bn2_m + l * EMB, vn_bn2_v + l * EMB,
                vn, pooled, nullptr, nullptr, NGRAPH, KP2, EMB, EMB, 1, 2);
        }
    }

    k_final_zero<<<gVN, T>>>(out, counts);
    k_final_acc<<<gN, T>>>(h, batch, out, counts, N);
    k_final_div<<<gVN, T>>>(out, counts);
}

// round 12
// speedup vs baseline: 2.4160x; 1.1564x over previous
#include <cuda_runtime.h>
#include <cuda_bf16.h>
#include <math.h>
#include <cstdint>

// ---------------- problem constants ----------------
#define EMB        300
#define C4         75
#define NLAYERS    5
#define NGRAPH     4096
#define ATOM_F     9
#define ATOM_V     128
#define BOND_V     8
#define BN_EPS     1e-5f
#define NMAX       100000
#define EMAX       250000
#define KP1        320
#define KP2        608

// ---------------- device scratch ----------------
__device__ __align__(16) float g_h     [(size_t)NMAX * EMB];
__device__ __align__(16) float g_agg   [(size_t)NMAX * EMB];
__device__ __align__(16) float g_vn    [(size_t)NGRAPH * EMB];
__device__ __align__(16) float g_pooled[(size_t)NGRAPH * EMB];
__device__            float g_counts[NGRAPH];
__device__ __align__(16) __nv_bfloat16 g_agg_h[(size_t)NMAX * KP1];
__device__ __align__(16) __nv_bfloat16 g_agg_l[(size_t)NMAX * KP1];
__device__ __align__(16) __nv_bfloat16 g_t1_h [(size_t)NMAX * KP2];
__device__ __align__(16) __nv_bfloat16 g_t1_l [(size_t)NMAX * KP2];
__device__ __align__(16) __nv_bfloat16 g_pl_h [(size_t)NGRAPH * KP1];
__device__ __align__(16) __nv_bfloat16 g_pl_l [(size_t)NGRAPH * KP1];
__device__ __align__(16) __nv_bfloat16 g_vnt_h[(size_t)NGRAPH * KP2];
__device__ __align__(16) __nv_bfloat16 g_vnt_l[(size_t)NGRAPH * KP2];
__device__ __align__(16) __nv_bfloat16 g_w1t_h[(size_t)NLAYERS * 2 * EMB * KP1];
__device__ __align__(16) __nv_bfloat16 g_w1t_l[(size_t)NLAYERS * 2 * EMB * KP1];
__device__ __align__(16) __nv_bfloat16 g_w2t_h[(size_t)NLAYERS * EMB * KP2];
__device__ __align__(16) __nv_bfloat16 g_w2t_l[(size_t)NLAYERS * EMB * KP2];
__device__ __align__(16) __nv_bfloat16 g_wv1_h[(size_t)(NLAYERS - 1) * 2 * EMB * KP1];
__device__ __align__(16) __nv_bfloat16 g_wv1_l[(size_t)(NLAYERS - 1) * 2 * EMB * KP1];
__device__ __align__(16) __nv_bfloat16 g_wv2_h[(size_t)(NLAYERS - 1) * EMB * KP2];
__device__ __align__(16) __nv_bfloat16 g_wv2_l[(size_t)(NLAYERS - 1) * EMB * KP2];

__device__ __forceinline__ uint32_t smem_u32(const void* p) {
    uint32_t a;
    asm("{ .reg .u64 t; cvta.to.shared.u64 t, %1; cvt.u32.u64 %0, t; }" : "=r"(a) : "l"(p));
    return a;
}

#define LDSM4(r, a) asm volatile( \
    "ldmatrix.sync.aligned.m8n8.x4.shared.b16 {%0,%1,%2,%3},[%4];" \
    : "=r"((r)[0]),"=r"((r)[1]),"=r"((r)[2]),"=r"((r)[3]) : "r"(a))
#define MMA16816(c, a, b) asm volatile( \
    "mma.sync.aligned.m16n8k16.row.col.f32.bf16.bf16.f32 " \
    "{%0,%1,%2,%3},{%4,%5,%6,%7},{%8,%9},{%0,%1,%2,%3};" \
    : "+f"((c)[0]),"+f"((c)[1]),"+f"((c)[2]),"+f"((c)[3]) \
    : "r"((a)[0]),"r"((a)[1]),"r"((a)[2]),"r"((a)[3]),"r"((b)[0]),"r"((b)[1]))
#define CP_ASYNC16(saddr, gptr, ssz) asm volatile( \
    "cp.async.cg.shared.global [%0], [%1], 16, %2;" \
    :: "r"(saddr), "l"(gptr), "r"(ssz))
#define CP_COMMIT() asm volatile("cp.async.commit_group;" ::: "memory")
#define CP_WAIT0()  asm volatile("cp.async.wait_group 0;" ::: "memory")
#define REDV4(p, a, b, c, d) asm volatile( \
    "red.global.add.v4.f32 [%0], {%1,%2,%3,%4};" \
    :: "l"(p), "f"(a), "f"(b), "f"(c), "f"(d) : "memory")
#define REDV2(p, a, b) asm volatile( \
    "red.global.add.v2.f32 [%0], {%1,%2};" \
    :: "l"(p), "f"(a), "f"(b) : "memory")

// ---------------- atom encoder ----------------
__global__ void k_atom_encode(const int* __restrict__ x, const float* __restrict__ atom_emb,
                              float* __restrict__ h, int N) {
    int idx = blockIdx.x * blockDim.x + threadIdx.x;
    if (idx >= N * C4) return;
    int n = idx / C4, c = idx % C4;
    float4 acc = make_float4(0.f, 0.f, 0.f, 0.f);
#pragma unroll
    for (int f = 0; f < ATOM_F; f++) {
        int a = x[n * ATOM_F + f];
        float4 v = *(const float4*)(atom_emb + ((size_t)(f * ATOM_V + a)) * EMB + c * 4);
        acc.x += v.x; acc.y += v.y; acc.z += v.z; acc.w += v.w;
    }
    *(float4*)(h + (size_t)n * EMB + c * 4) = acc;
}

// vn_init also initializes pooled (= vn)
__global__ void k_vn_init(const float* __restrict__ vn_emb, float* __restrict__ vn,
                          float* __restrict__ pooled) {
    int idx = blockIdx.x * blockDim.x + threadIdx.x;
    if (idx >= NGRAPH * EMB) return;
    float v = vn_emb[idx % EMB];
    vn[idx] = v;
    pooled[idx] = v;
}

// ---------------- layer-0 only: h += vn_emb (uniform); agg=(1+eps0)h; pooled += h ----------------
__global__ void k_vnadd0(float* __restrict__ h, float* __restrict__ agg,
                         const float* __restrict__ vn_emb, const int* __restrict__ batch,
                         float* __restrict__ pooled, const float* __restrict__ gin_eps, int N) {
    int idx = blockIdx.x * blockDim.x + threadIdx.x;
    if (idx >= N * C4) return;
    int n = idx / C4, c = idx % C4;
    int b = batch[n];
    float oe = 1.f + gin_eps[0];
    float4 hv = *(float4*)(h + (size_t)n * EMB + c * 4);
    float4 vv = *(const float4*)(vn_emb + c * 4);
    hv.x += vv.x; hv.y += vv.y; hv.z += vv.z; hv.w += vv.w;
    *(float4*)(h + (size_t)n * EMB + c * 4) = hv;
    float4 av = make_float4(hv.x * oe, hv.y * oe, hv.z * oe, hv.w * oe);
    *(float4*)(agg + (size_t)n * EMB + c * 4) = av;
    REDV4(pooled + (size_t)b * EMB + c * 4, hv.x, hv.y, hv.z, hv.w);
}

// ---------------- weight transpose + split (gin + vn weights) ----------------
__global__ void k_prep_w(const float* __restrict__ W1, const float* __restrict__ W2,
                         const float* __restrict__ V1, const float* __restrict__ V2,
                         __nv_bfloat16* __restrict__ w1h, __nv_bfloat16* __restrict__ w1l,
                         __nv_bfloat16* __restrict__ w2h, __nv_bfloat16* __restrict__ w2l,
                         __nv_bfloat16* __restrict__ v1h, __nv_bfloat16* __restrict__ v1l,
                         __nv_bfloat16* __restrict__ v2h, __nv_bfloat16* __restrict__ v2l) {
    const int SZ1 = NLAYERS * 2 * EMB * KP1;
    const int SZ2 = NLAYERS * EMB * KP2;
    const int SZ3 = (NLAYERS - 1) * 2 * EMB * KP1;
    const int SZ4 = (NLAYERS - 1) * EMB * KP2;
    int idx = blockIdx.x * blockDim.x + threadIdx.x;
    if (idx < SZ1) {
        int l = idx / (2 * EMB * KP1);
        int rem = idx % (2 * EMB * KP1);
        int n = rem / KP1, k = rem % KP1;
        float w = (k < EMB) ? W1[(size_t)l * EMB * 2 * EMB + (size_t)k * 2 * EMB + n] : 0.f;
        __nv_bfloat16 hi = __float2bfloat16(w);
        w1h[idx] = hi;
        w1l[idx] = __float2bfloat16(w - __bfloat162float(hi));
    } else if (idx < SZ1 + SZ2) {
        int j = idx - SZ1;
        int l = j / (EMB * KP2);
        int rem = j % (EMB * KP2);
        int n = rem / KP2, k = rem % KP2;
        float w = (k < 2 * EMB) ? W2[(size_t)l * 2 * EMB * EMB + (size_t)k * EMB + n] : 0.f;
        __nv_bfloat16 hi = __float2bfloat16(w);
        w2h[j] = hi;
        w2l[j] = __float2bfloat16(w - __bfloat162float(hi));
    } else if (idx < SZ1 + SZ2 + SZ3) {
        int j = idx - SZ1 - SZ2;
        int l = j / (2 * EMB * KP1);
        int rem = j % (2 * EMB * KP1);
        int n = rem / KP1, k = rem % KP1;
        float w = (k < EMB) ? V1[(size_t)l * EMB * 2 * EMB + (size_t)k * 2 * EMB + n] : 0.f;
        __nv_bfloat16 hi = __float2bfloat16(w);
        v1h[j] = hi;
        v1l[j] = __float2bfloat16(w - __bfloat162float(hi));
    } else if (idx < SZ1 + SZ2 + SZ3 + SZ4) {
        int j = idx - SZ1 - SZ2 - SZ3;
        int l = j / (EMB * KP2);
        int rem = j % (EMB * KP2);
        int n = rem / KP2, k = rem % KP2;
        float w = (k < 2 * EMB) ? V2[(size_t)l * 2 * EMB * EMB + (size_t)k * EMB + n] : 0.f;
        __nv_bfloat16 hi = __float2bfloat16(w);
        v2h[j] = hi;
        v2l[j] = __float2bfloat16(w - __bfloat162float(hi));
    }
}

// ---------------- fp32 [N,EMB] -> bf16 hi/lo [N,KP1] ----------------
__global__ void k_split(const float* __restrict__ src, __nv_bfloat16* __restrict__ dh,
                        __nv_bfloat16* __restrict__ dl, int N) {
    int idx = blockIdx.x * blockDim.x + threadIdx.x;
    if (idx >= N * KP1) return;
    int n = idx / KP1, k = idx % KP1;
    float v = (k < EMB) ? src[(size_t)n * EMB + k] : 0.f;
    __nv_bfloat16 hi = __float2bfloat16(v);
    dh[idx] = hi;
    dl[idx] = __float2bfloat16(v - __bfloat162float(hi));
}

// ---------------- edge scatter (vector atomics) ----------------
__global__ void k_edge_scatter(const float* __restrict__ h, float* __restrict__ agg,
                               const int* __restrict__ ei, const int* __restrict__ ea,
                               const float* __restrict__ bond_emb, int E) {
    int idx = blockIdx.x * blockDim.x + threadIdx.x;
    if (idx >= E * C4) return;
    int e = idx / C4, c = idx % C4;
    int row = ei[e];
    int col = ei[E + e];
    int a0 = ea[e * 3 + 0], a1 = ea[e * 3 + 1], a2 = ea[e * 3 + 2];
    float4 hv = *(const float4*)(h + (size_t)row * EMB + c * 4);
    float4 b0 = *(const float4*)(bond_emb + (size_t)(0 * BOND_V + a0) * EMB + c * 4);
    float4 b1 = *(const float4*)(bond_emb + (size_t)(1 * BOND_V + a1) * EMB + c * 4);
    float4 b2 = *(const float4*)(bond_emb + (size_t)(2 * BOND_V + a2) * EMB + c * 4);
    float mx = fmaxf(hv.x + b0.x + b1.x + b2.x, 0.f);
    float my = fmaxf(hv.y + b0.y + b1.y + b2.y, 0.f);
    float mz = fmaxf(hv.z + b0.z + b1.z + b2.z, 0.f);
    float mw = fmaxf(hv.w + b0.w + b1.w + b2.w, 0.f);
    REDV4(agg + (size_t)col * EMB + c * 4, mx, my, mz, mw);
}

// ================= bf16-split tensor-core GEMM, 128x128x32, cp.async 2-stage =================
// mode 0: fp32 bn(+relu) -> out_f32
// mode 1: bf16 hi/lo split -> out_hi/out_lo (stride ldo, pads zeroed)
// mode 2: fp32 bn(+relu) -> out_f32 AND out_f32b
// mode 3: fused GIN epilogue: hn = bn+relu; h = hn + vn_next[batch]; out_f32=h;
//         out_f32b = (1+eps_next)*h; pooled += h (vector atomics)
#define MM_BM 128
#define MM_BN 128
#define MM_BK 32
#define ROWB  80
#define SA_H  0
#define SA_L  10240
#define SB_H  20480
#define SB_L  30720
#define STAGE 40960
#define EPI_SC 81920
#define EPI_OF 82432
#define SMEM_TOT 82944

__global__ void __launch_bounds__(256, 2)
k_mma_gemm(const __nv_bfloat16* __restrict__ Ah, const __nv_bfloat16* __restrict__ Al,
           const __nv_bfloat16* __restrict__ Bh, const __nv_bfloat16* __restrict__ Bl,
           const float* __restrict__ bias,
           const float* __restrict__ bng, const float* __restrict__ bnb,
           const float* __restrict__ bnm, const float* __restrict__ bnv,
           float* __restrict__ out_f32, float* __restrict__ out_f32b,
           __nv_bfloat16* __restrict__ out_hi, __nv_bfloat16* __restrict__ out_lo,
           const int* __restrict__ batch, const float* __restrict__ vnp,
           float* __restrict__ pooledp, const float* __restrict__ epsp,
           int M, int Kpad, int Nc, int ldo, int do_relu, int mode) {
    extern __shared__ char sm[];
    const uint32_t smb = smem_u32(sm);
    const int tid = threadIdx.x;
    const int lane = tid & 31;
    const int warp = tid >> 5;
    const int warp_m = warp & 3;
    const int warp_n = warp >> 2;
    const int row0 = blockIdx.y * MM_BM;
    const int col0 = blockIdx.x * MM_BN;

    float* scp = (float*)(sm + EPI_SC);
    float* ofp = (float*)(sm + EPI_OF);
    if (tid < MM_BN) {
        int gn = col0 + tid;
        float s = 0.f, o = 0.f;
        if (gn < Nc) {
            s = bng[gn] * rsqrtf(bnv[gn] + BN_EPS);
            o = bias[gn] * s + bnb[gn] - bnm[gn] * s;
        }
        scp[tid] = s;
        ofp[tid] = o;
    }

    float acc[2][8][4];
#pragma unroll
    for (int mi = 0; mi < 2; mi++)
#pragma unroll
        for (int ci = 0; ci < 8; ci++)
#pragma unroll
            for (int q = 0; q < 4; q++) acc[mi][ci][q] = 0.f;

    const int r0i = tid >> 2, s0i = tid & 3;
    const int r1i = (tid + 256) >> 2, s1i = (tid + 256) & 3;
    const int gmA0 = row0 + r0i, gmA1 = row0 + r1i;
    const int gnB0 = col0 + r0i, gnB1 = col0 + r1i;
    const uint32_t szA0 = (gmA0 < M) ? 16u : 0u, szA1 = (gmA1 < M) ? 16u : 0u;
    const uint32_t szB0 = (gnB0 < Nc) ? 16u : 0u, szB1 = (gnB1 < Nc) ? 16u : 0u;
    const size_t oA0 = (size_t)min(gmA0, M - 1) * Kpad + s0i * 8;
    const size_t oA1 = (size_t)min(gmA1, M - 1) * Kpad + s1i * 8;
    const size_t oB0 = (size_t)min(gnB0, Nc - 1) * Kpad + s0i * 8;
    const size_t oB1 = (size_t)min(gnB1, Nc - 1) * Kpad + s1i * 8;
    const uint32_t dA0 = r0i * ROWB + s0i * 16, dA1 = r1i * ROWB + s1i * 16;

#define ISSUE(ch, st) do { \
    const int _k0 = (ch) * MM_BK; \
    const uint32_t _sb = smb + (st) * STAGE; \
    CP_ASYNC16(_sb + SA_H + dA0, Ah + oA0 + _k0, szA0); \
    CP_ASYNC16(_sb + SA_H + dA1, Ah + oA1 + _k0, szA1); \
    CP_ASYNC16(_sb + SA_L + dA0, Al + oA0 + _k0, szA0); \
    CP_ASYNC16(_sb + SA_L + dA1, Al + oA1 + _k0, szA1); \
    CP_ASYNC16(_sb + SB_H + dA0, Bh + oB0 + _k0, szB0); \
    CP_ASYNC16(_sb + SB_H + dA1, Bh + oB1 + _k0, szB1); \
    CP_ASYNC16(_sb + SB_L + dA0, Bl + oB0 + _k0, szB0); \
    CP_ASYNC16(_sb + SB_L + dA1, Bl + oB1 + _k0, szB1); \
    CP_COMMIT(); \
} while (0)

    const uint32_t aoff = (warp_m * 32 + (lane & 15)) * ROWB + (lane >> 4) * 16;
    const uint32_t boff = (warp_n * 64 + (lane & 7) + ((lane >> 4) << 3)) * ROWB
                        + ((lane >> 3) & 1) * 16;

    const int nk = Kpad / MM_BK;
    ISSUE(0, 0);
    for (int ch = 0; ch < nk; ch++) {
        const int st = ch & 1;
        CP_WAIT0();
        __syncthreads();
        if (ch + 1 < nk) ISSUE(ch + 1, st ^ 1);

        const uint32_t a_h = smb + st * STAGE + SA_H;
        const uint32_t a_l = smb + st * STAGE + SA_L;
        const uint32_t b_h = smb + st * STAGE + SB_H;
        const uint32_t b_l = smb + st * STAGE + SB_L;
#pragma unroll
        for (int ks = 0; ks < 2; ks++) {
            const uint32_t ka = ks * 32;
            uint32_t ah0[4], ah1[4], al0[4], al1[4];
            LDSM4(ah0, a_h + aoff + ka);
            LDSM4(ah1, a_h + aoff + 16 * ROWB + ka);
            LDSM4(al0, a_l + aoff + ka);
            LDSM4(al1, a_l + aoff + 16 * ROWB + ka);
#pragma unroll
            for (int half = 0; half < 2; half++) {
                const int h4 = half * 4;
                uint32_t bh[2][4], bl[2][4];
                LDSM4(bh[0], b_h + boff + (half * 32 + 0) * ROWB + ka);
                LDSM4(bh[1], b_h + boff + (half * 32 + 16) * ROWB + ka);
                LDSM4(bl[0], b_l + boff + (half * 32 + 0) * ROWB + ka);
                LDSM4(bl[1], b_l + boff + (half * 32 + 16) * ROWB + ka);
#define COMBO(AF0, AF1, BF) \
                MMA16816(acc[0][h4 + 0], AF0, (BF[0] + 0)); \
                MMA16816(acc[1][h4 + 0], AF1, (BF[0] + 0)); \
                MMA16816(acc[0][h4 + 1], AF0, (BF[0] + 2)); \
                MMA16816(acc[1][h4 + 1], AF1, (BF[0] + 2)); \
                MMA16816(acc[0][h4 + 2], AF0, (BF[1] + 0)); \
                MMA16816(acc[1][h4 + 2], AF1, (BF[1] + 0)); \
                MMA16816(acc[0][h4 + 3], AF0, (BF[1] + 2)); \
                MMA16816(acc[1][h4 + 3], AF1, (BF[1] + 2));
                COMBO(ah0, ah1, bh)
                COMBO(ah0, ah1, bl)
                COMBO(al0, al1, bh)
#undef COMBO
            }
        }
        __syncthreads();
    }

    // ---- epilogue ----
    const int tg = lane >> 2;
    const int np = (lane & 3) * 2;
    const float oe = (mode == 3) ? (1.f + __ldg(epsp)) : 0.f;
#pragma unroll
    for (int mi = 0; mi < 2; mi++) {
        const int rb = row0 + warp_m * 32 + mi * 16 + tg;
        int bA = 0, bB = 0;
        if (mode == 3) {
            bA = (rb < M) ? batch[rb] : 0;
            bB = (rb + 8 < M) ? batch[rb + 8] : 0;
        }
#pragma unroll
        for (int ci8 = 0; ci8 < 8; ci8++) {
            int ci = warp_n * 64 + ci8 * 8 + np;
            int gn = col0 + ci;
            float s0 = scp[ci], s1 = scp[ci + 1];
            float o0 = ofp[ci], o1 = ofp[ci + 1];
#pragma unroll
            for (int hb = 0; hb < 2; hb++) {
                int r = rb + hb * 8;
                if (r >= M) continue;
                float v0 = acc[mi][ci8][hb * 2 + 0] * s0 + o0;
                float v1 = acc[mi][ci8][hb * 2 + 1] * s1 + o1;
                if (do_relu) { v0 = fmaxf(v0, 0.f); v1 = fmaxf(v1, 0.f); }
                if (mode == 1) {
                    if (gn < ldo) {
                        __nv_bfloat16 h0 = __float2bfloat16(v0);
                        __nv_bfloat16 h1 = __float2bfloat16(v1);
                        __nv_bfloat162 hp; hp.x = h0; hp.y = h1;
                        __nv_bfloat162 lp;
                        lp.x = __float2bfloat16(v0 - __bfloat162float(h0));
                        lp.y = __float2bfloat16(v1 - __bfloat162float(h1));
                        *(__nv_bfloat162*)(out_hi + (size_t)r * ldo + gn) = hp;
                        *(__nv_bfloat162*)(out_lo + (size_t)r * ldo + gn) = lp;
                    }
                } else if (mode == 3) {
                    if (gn < Nc) {
                        int b = hb ? bB : bA;
                        float2 vv = *(const float2*)(vnp + (size_t)b * EMB + gn);
                        float h0 = v0 + vv.x;
                        float h1 = v1 + vv.y;
                        float2 hw; hw.x = h0; hw.y = h1;
                        *(float2*)(out_f32 + (size_t)r * Nc + gn) = hw;
                        float2 aw; aw.x = h0 * oe; aw.y = h1 * oe;
                        *(float2*)(out_f32b + (size_t)r * Nc + gn) = aw;
                        REDV2(pooledp + (size_t)b * EMB + gn, h0, h1);
                    }
                } else {
                    if (gn < Nc) {
                        float2 fv; fv.x = v0; fv.y = v1;
                        *(float2*)(out_f32 + (size_t)r * Nc + gn) = fv;
                        if (mode == 2)
                            *(float2*)(out_f32b + (size_t)r * Nc + gn) = fv;
                    }
                }
            }
        }
    }
}

// ---------------- final mean pool ----------------
__global__ void k_final_zero(float* __restrict__ out, float* __restrict__ counts) {
    int idx = blockIdx.x * blockDim.x + threadIdx.x;
    if (idx < NGRAPH * EMB) out[idx] = 0.f;
    if (idx < NGRAPH) counts[idx] = 0.f;
}
__global__ void k_final_acc(const float* __restrict__ h, const int* __restrict__ batch,
                            float* __restrict__ out, float* __restrict__ counts, int N) {
    int idx = blockIdx.x * blockDim.x + threadIdx.x;
    if (idx >= N * C4) return;
    int n = idx / C4, c = idx % C4;
    int b = batch[n];
    float4 hv = *(const float4*)(h + (size_t)n * EMB + c * 4);
    REDV4(out + (size_t)b * EMB + c * 4, hv.x, hv.y, hv.z, hv.w);
    if (c == 0) atomicAdd(counts + b, 1.f);
}
__global__ void k_final_div(float* __restrict__ out, const float* __restrict__ counts) {
    int idx = blockIdx.x * blockDim.x + threadIdx.x;
    if (idx >= NGRAPH * EMB) return;
    int g = idx / EMB;
    out[idx] /= fmaxf(counts[g], 1.f);
}

static inline dim3 mma_grid(int M, int Nc) {
    return dim3((Nc + MM_BN - 1) / MM_BN, (M + MM_BM - 1) / MM_BM);
}

extern "C" void kernel_launch(void* const* d_in, const int* in_sizes, int n_in,
                              void* d_out, int out_size) {
    const int*   x        = (const int*)  d_in[0];
    const int*   ei       = (const int*)  d_in[1];
    const int*   ea       = (const int*)  d_in[2];
    const int*   batch    = (const int*)  d_in[3];
    const float* atom_emb = (const float*)d_in[4];
    const float* bond_emb = (const float*)d_in[5];
    const float* vn_emb   = (const float*)d_in[6];
    const float* gin_eps  = (const float*)d_in[7];
    const float* gin_W1   = (const float*)d_in[8];
    const float* gin_b1   = (const float*)d_in[9];
    const float* gin_bn1_g= (const float*)d_in[10];
    const float* gin_bn1_b= (const float*)d_in[11];
    const float* gin_bn1_m= (const float*)d_in[12];
    const float* gin_bn1_v= (const float*)d_in[13];
    const float* gin_W2   = (const float*)d_in[14];
    const float* gin_b2   = (const float*)d_in[15];
    const float* bn_g     = (const float*)d_in[16];
    const float* bn_b     = (const float*)d_in[17];
    const float* bn_m     = (const float*)d_in[18];
    const float* bn_v     = (const float*)d_in[19];
    const float* vn_W1    = (const float*)d_in[20];
    const float* vn_b1    = (const float*)d_in[21];
    const float* vn_bn1_g = (const float*)d_in[22];
    const float* vn_bn1_b = (const float*)d_in[23];
    const float* vn_bn1_m = (const float*)d_in[24];
    const float* vn_bn1_v = (const float*)d_in[25];
    const float* vn_W2    = (const float*)d_in[26];
    const float* vn_b2    = (const float*)d_in[27];
    const float* vn_bn2_g = (const float*)d_in[28];
    const float* vn_bn2_b = (const float*)d_in[29];
    const float* vn_bn2_m = (const float*)d_in[30];
    const float* vn_bn2_v = (const float*)d_in[31];

    const int N = in_sizes[0] / ATOM_F;
    const int E = in_sizes[1] / 2;
    float* out = (float*)d_out;

    float *h, *agg, *vn, *pooled, *counts;
    __nv_bfloat16 *aggh, *aggl, *t1h, *t1l, *plh, *pll, *vnth, *vntl;
    __nv_bfloat16 *w1h, *w1l, *w2h, *w2l, *v1h, *v1l, *v2h, *v2l;
    cudaGetSymbolAddress((void**)&h,      g_h);
    cudaGetSymbolAddress((void**)&agg,    g_agg);
    cudaGetSymbolAddress((void**)&vn,     g_vn);
    cudaGetSymbolAddress((void**)&pooled, g_pooled);
    cudaGetSymbolAddress((void**)&counts, g_counts);
    cudaGetSymbolAddress((void**)&aggh,   g_agg_h);
    cudaGetSymbolAddress((void**)&aggl,   g_agg_l);
    cudaGetSymbolAddress((void**)&t1h,    g_t1_h);
    cudaGetSymbolAddress((void**)&t1l,    g_t1_l);
    cudaGetSymbolAddress((void**)&plh,    g_pl_h);
    cudaGetSymbolAddress((void**)&pll,    g_pl_l);
    cudaGetSymbolAddress((void**)&vnth,   g_vnt_h);
    cudaGetSymbolAddress((void**)&vntl,   g_vnt_l);
    cudaGetSymbolAddress((void**)&w1h,    g_w1t_h);
    cudaGetSymbolAddress((void**)&w1l,    g_w1t_l);
    cudaGetSymbolAddress((void**)&w2h,    g_w2t_h);
    cudaGetSymbolAddress((void**)&w2l,    g_w2t_l);
    cudaGetSymbolAddress((void**)&v1h,    g_wv1_h);
    cudaGetSymbolAddress((void**)&v1l,    g_wv1_l);
    cudaGetSymbolAddress((void**)&v2h,    g_wv2_h);
    cudaGetSymbolAddress((void**)&v2l,    g_wv2_l);

    cudaFuncSetAttribute(k_mma_gemm, cudaFuncAttributeMaxDynamicSharedMemorySize, SMEM_TOT);

    const int T = 256;
    const int gN  = (N * C4 + T - 1) / T;
    const int gE  = (E * C4 + T - 1) / T;
    const int gVN = (NGRAPH * EMB + T - 1) / T;
    const int WTOT = NLAYERS * 2 * EMB * KP1 + NLAYERS * EMB * KP2
                   + (NLAYERS - 1) * 2 * EMB * KP1 + (NLAYERS - 1) * EMB * KP2;

    // launch order keeps k_edge_scatter at index 3 (ncu slot)
    k_atom_encode<<<gN, T>>>(x, atom_emb, h, N);                       // 0
    k_vn_init<<<gVN, T>>>(vn_emb, vn, pooled);                         // 1
    k_vnadd0<<<gN, T>>>(h, agg, vn_emb, batch, pooled, gin_eps, N);    // 2

    for (int l = 0; l < NLAYERS; l++) {
        const int do_pool = (l < NLAYERS - 1);
        k_edge_scatter<<<gE, T>>>(h, agg, ei, ea, bond_emb, E);        // l=0: 3
        if (l == 0)
            k_prep_w<<<(WTOT + T - 1) / T, T>>>(gin_W1, gin_W2, vn_W1, vn_W2,
                                                w1h, w1l, w2h, w2l, v1h, v1l, v2h, v2l);
        k_split<<<(N * KP1 + T - 1) / T, T>>>(agg, aggh, aggl, N);
        // GEMM1: t1(hi/lo) = relu(bn1(agg @ W1 + b1))
        k_mma_gemm<<<mma_grid(N, 2 * EMB), 256, SMEM_TOT>>>(
            aggh, aggl, w1h + (size_t)l * 2 * EMB * KP1, w1l + (size_t)l * 2 * EMB * KP1,
            gin_b1 + l * 2 * EMB,
            gin_bn1_g + l * 2 * EMB, gin_bn1_b + l * 2 * EMB,
            gin_bn1_m + l * 2 * EMB, gin_bn1_v + l * 2 * EMB,
            nullptr, nullptr, t1h, t1l, nullptr, nullptr, nullptr, nullptr,
            N, KP1, 2 * EMB, KP2, 1, 1);
        if (do_pool) {
            // vn MLP (produces vn_{l+1}; mode 2 also resets pooled = vn_{l+1})
            k_split<<<(NGRAPH * KP1 + T - 1) / T, T>>>(pooled, plh, pll, NGRAPH);
            k_mma_gemm<<<mma_grid(NGRAPH, 2 * EMB), 256, SMEM_TOT>>>(
                plh, pll, v1h + (size_t)l * 2 * EMB * KP1, v1l + (size_t)l * 2 * EMB * KP1,
                vn_b1 + l * 2 * EMB,
                vn_bn1_g + l * 2 * EMB, vn_bn1_b + l * 2 * EMB,
                vn_bn1_m + l * 2 * EMB, vn_bn1_v + l * 2 * EMB,
                nullptr, nullptr, vnth, vntl, nullptr, nullptr, nullptr, nullptr,
                NGRAPH, KP1, 2 * EMB, KP2, 1, 1);
            k_mma_gemm<<<mma_grid(NGRAPH, EMB), 256, SMEM_TOT>>>(
                vnth, vntl, v2h + (size_t)l * EMB * KP2, v2l + (size_t)l * EMB * KP2,
                vn_b2 + l * EMB,
                vn_bn2_g + l * EMB, vn_bn2_b + l * EMB,
                vn_bn2_m + l * EMB, vn_bn2_v + l * EMB,
                vn, pooled, nullptr, nullptr, nullptr, nullptr, nullptr, nullptr,
                NGRAPH, KP2, EMB, EMB, 1, 2);
            // GEMM2 fused (mode 3): h = relu(bn(t1@W2+b2)) + vn_{l+1}[batch];
            // agg = (1+eps_{l+1})*h; pooled += h
            k_mma_gemm<<<mma_grid(N, EMB), 256, SMEM_TOT>>>(
                t1h, t1l, w2h + (size_t)l * EMB * KP2, w2l + (size_t)l * EMB * KP2,
                gin_b2 + l * EMB,
                bn_g + l * EMB, bn_b + l * EMB, bn_m + l * EMB, bn_v + l * EMB,
                h, agg, nullptr, nullptr, batch, vn, pooled, gin_eps + (l + 1),
                N, KP2, EMB, EMB, 1, 3);
        } else {
            // last layer: plain h = bn(t1@W2+b2), no relu
            k_mma_gemm<<<mma_grid(N, EMB), 256, SMEM_TOT>>>(
                t1h, t1l, w2h + (size_t)l * EMB * KP2, w2l + (size_t)l * EMB * KP2,
                gin_b2 + l * EMB,
                bn_g + l * EMB, bn_b + l * EMB, bn_m + l * EMB, bn_v + l * EMB,
                h, nullptr, nullptr, nullptr, nullptr, nullptr, nullptr, nullptr,
                N, KP2, EMB, EMB, 0, 0);
        }
    }

    k_final_zero<<<gVN, T>>>(out, counts);
    k_final_acc<<<gN, T>>>(h, batch, out, counts, N);
    k_final_div<<<gVN, T>>>(out, counts);
}

// round 15
// speedup vs baseline: 2.5752x; 1.0659x over previous
#include <cuda_runtime.h>
#include <cuda_bf16.h>
#include <math.h>
#include <cstdint>

// ---------------- problem constants ----------------
#define EMB        300
#define C4         75
#define NLAYERS    5
#define NGRAPH     4096
#define ATOM_F     9
#define ATOM_V     128
#define BOND_V     8
#define BN_EPS     1e-5f
#define NMAX       100000
#define EMAX       250000
#define KP1        320
#define KP2        608

// ---------------- device scratch ----------------
__device__ __align__(16) float g_h     [(size_t)NMAX * EMB];
__device__ __align__(16) float g_agg   [(size_t)NMAX * EMB];
__device__ __align__(16) float g_vn    [(size_t)NGRAPH * EMB];
__device__ __align__(16) float g_pooled[(size_t)NGRAPH * EMB];
__device__            float g_counts[NGRAPH];
__device__ __align__(16) __nv_bfloat16 g_agg_h[(size_t)NMAX * KP1];
__device__ __align__(16) __nv_bfloat16 g_agg_l[(size_t)NMAX * KP1];
__device__ __align__(16) __nv_bfloat16 g_t1_h [(size_t)NMAX * KP2];
__device__ __align__(16) __nv_bfloat16 g_t1_l [(size_t)NMAX * KP2];
__device__ __align__(16) __nv_bfloat16 g_pl_h [(size_t)NGRAPH * KP1];
__device__ __align__(16) __nv_bfloat16 g_pl_l [(size_t)NGRAPH * KP1];
__device__ __align__(16) __nv_bfloat16 g_vnt_h[(size_t)NGRAPH * KP2];
__device__ __align__(16) __nv_bfloat16 g_vnt_l[(size_t)NGRAPH * KP2];
__device__ __align__(16) __nv_bfloat16 g_w1t_h[(size_t)NLAYERS * 2 * EMB * KP1];
__device__ __align__(16) __nv_bfloat16 g_w1t_l[(size_t)NLAYERS * 2 * EMB * KP1];
__device__ __align__(16) __nv_bfloat16 g_w2t_h[(size_t)NLAYERS * EMB * KP2];
__device__ __align__(16) __nv_bfloat16 g_w2t_l[(size_t)NLAYERS * EMB * KP2];
__device__ __align__(16) __nv_bfloat16 g_wv1_h[(size_t)(NLAYERS - 1) * 2 * EMB * KP1];
__device__ __align__(16) __nv_bfloat16 g_wv1_l[(size_t)(NLAYERS - 1) * 2 * EMB * KP1];
__device__ __align__(16) __nv_bfloat16 g_wv2_h[(size_t)(NLAYERS - 1) * EMB * KP2];
__device__ __align__(16) __nv_bfloat16 g_wv2_l[(size_t)(NLAYERS - 1) * EMB * KP2];

__device__ __forceinline__ uint32_t smem_u32(const void* p) {
    uint32_t a;
    asm("{ .reg .u64 t; cvta.to.shared.u64 t, %1; cvt.u32.u64 %0, t; }" : "=r"(a) : "l"(p));
    return a;
}

#define LDSM4(r, a) asm volatile( \
    "ldmatrix.sync.aligned.m8n8.x4.shared.b16 {%0,%1,%2,%3},[%4];" \
    : "=r"((r)[0]),"=r"((r)[1]),"=r"((r)[2]),"=r"((r)[3]) : "r"(a))
#define MMA16816(c, a, b) asm volatile( \
    "mma.sync.aligned.m16n8k16.row.col.f32.bf16.bf16.f32 " \
    "{%0,%1,%2,%3},{%4,%5,%6,%7},{%8,%9},{%0,%1,%2,%3};" \
    : "+f"((c)[0]),"+f"((c)[1]),"+f"((c)[2]),"+f"((c)[3]) \
    : "r"((a)[0]),"r"((a)[1]),"r"((a)[2]),"r"((a)[3]),"r"((b)[0]),"r"((b)[1]))
#define CP_ASYNC16(saddr, gptr, ssz) asm volatile( \
    "cp.async.cg.shared.global [%0], [%1], 16, %2;" \
    :: "r"(saddr), "l"(gptr), "r"(ssz))
#define CP_COMMIT() asm volatile("cp.async.commit_group;" ::: "memory")
#define CP_WAIT0()  asm volatile("cp.async.wait_group 0;" ::: "memory")
#define REDV4(p, a, b, c, d) asm volatile( \
    "red.global.add.v4.f32 [%0], {%1,%2,%3,%4};" \
    :: "l"(p), "f"(a), "f"(b), "f"(c), "f"(d) : "memory")
#define REDV2(p, a, b) asm volatile( \
    "red.global.add.v2.f32 [%0], {%1,%2};" \
    :: "l"(p), "f"(a), "f"(b) : "memory")

// ---------------- atom encoder ----------------
__global__ void k_atom_encode(const int* __restrict__ x, const float* __restrict__ atom_emb,
                              float* __restrict__ h, int N) {
    int idx = blockIdx.x * blockDim.x + threadIdx.x;
    if (idx >= N * C4) return;
    int n = idx / C4, c = idx % C4;
    float4 acc = make_float4(0.f, 0.f, 0.f, 0.f);
#pragma unroll
    for (int f = 0; f < ATOM_F; f++) {
        int a = x[n * ATOM_F + f];
        float4 v = *(const float4*)(atom_emb + ((size_t)(f * ATOM_V + a)) * EMB + c * 4);
        acc.x += v.x; acc.y += v.y; acc.z += v.z; acc.w += v.w;
    }
    *(float4*)(h + (size_t)n * EMB + c * 4) = acc;
}

// vn_init also initializes pooled (= vn)
__global__ void k_vn_init(const float* __restrict__ vn_emb, float* __restrict__ vn,
                          float* __restrict__ pooled) {
    int idx = blockIdx.x * blockDim.x + threadIdx.x;
    if (idx >= NGRAPH * EMB) return;
    float v = vn_emb[idx % EMB];
    vn[idx] = v;
    pooled[idx] = v;
}

// ---------------- layer-0 only: h += vn_emb (uniform); agg=(1+eps0)h; pooled += h ----------------
__global__ void k_vnadd0(float* __restrict__ h, float* __restrict__ agg,
                         const float* __restrict__ vn_emb, const int* __restrict__ batch,
                         float* __restrict__ pooled, const float* __restrict__ gin_eps, int N) {
    int idx = blockIdx.x * blockDim.x + threadIdx.x;
    if (idx >= N * C4) return;
    int n = idx / C4, c = idx % C4;
    int b = batch[n];
    float oe = 1.f + gin_eps[0];
    float4 hv = *(float4*)(h + (size_t)n * EMB + c * 4);
    float4 vv = *(const float4*)(vn_emb + c * 4);
    hv.x += vv.x; hv.y += vv.y; hv.z += vv.z; hv.w += vv.w;
    *(float4*)(h + (size_t)n * EMB + c * 4) = hv;
    float4 av = make_float4(hv.x * oe, hv.y * oe, hv.z * oe, hv.w * oe);
    *(float4*)(agg + (size_t)n * EMB + c * 4) = av;
    REDV4(pooled + (size_t)b * EMB + c * 4, hv.x, hv.y, hv.z, hv.w);
}

// ---------------- weight transpose + split (gin + vn weights) ----------------
__global__ void k_prep_w(const float* __restrict__ W1, const float* __restrict__ W2,
                         const float* __restrict__ V1, const float* __restrict__ V2,
                         __nv_bfloat16* __restrict__ w1h, __nv_bfloat16* __restrict__ w1l,
                         __nv_bfloat16* __restrict__ w2h, __nv_bfloat16* __restrict__ w2l,
                         __nv_bfloat16* __restrict__ v1h, __nv_bfloat16* __restrict__ v1l,
                         __nv_bfloat16* __restrict__ v2h, __nv_bfloat16* __restrict__ v2l) {
    const int SZ1 = NLAYERS * 2 * EMB * KP1;
    const int SZ2 = NLAYERS * EMB * KP2;
    const int SZ3 = (NLAYERS - 1) * 2 * EMB * KP1;
    const int SZ4 = (NLAYERS - 1) * EMB * KP2;
    int idx = blockIdx.x * blockDim.x + threadIdx.x;
    if (idx < SZ1) {
        int l = idx / (2 * EMB * KP1);
        int rem = idx % (2 * EMB * KP1);
        int n = rem / KP1, k = rem % KP1;
        float w = (k < EMB) ? W1[(size_t)l * EMB * 2 * EMB + (size_t)k * 2 * EMB + n] : 0.f;
        __nv_bfloat16 hi = __float2bfloat16(w);
        w1h[idx] = hi;
        w1l[idx] = __float2bfloat16(w - __bfloat162float(hi));
    } else if (idx < SZ1 + SZ2) {
        int j = idx - SZ1;
        int l = j / (EMB * KP2);
        int rem = j % (EMB * KP2);
        int n = rem / KP2, k = rem % KP2;
        float w = (k < 2 * EMB) ? W2[(size_t)l * 2 * EMB * EMB + (size_t)k * EMB + n] : 0.f;
        __nv_bfloat16 hi = __float2bfloat16(w);
        w2h[j] = hi;
        w2l[j] = __float2bfloat16(w - __bfloat162float(hi));
    } else if (idx < SZ1 + SZ2 + SZ3) {
        int j = idx - SZ1 - SZ2;
        int l = j / (2 * EMB * KP1);
        int rem = j % (2 * EMB * KP1);
        int n = rem / KP1, k = rem % KP1;
        float w = (k < EMB) ? V1[(size_t)l * EMB * 2 * EMB + (size_t)k * 2 * EMB + n] : 0.f;
        __nv_bfloat16 hi = __float2bfloat16(w);
        v1h[j] = hi;
        v1l[j] = __float2bfloat16(w - __bfloat162float(hi));
    } else if (idx < SZ1 + SZ2 + SZ3 + SZ4) {
        int j = idx - SZ1 - SZ2 - SZ3;
        int l = j / (EMB * KP2);
        int rem = j % (EMB * KP2);
        int n = rem / KP2, k = rem % KP2;
        float w = (k < 2 * EMB) ? V2[(size_t)l * 2 * EMB * EMB + (size_t)k * EMB + n] : 0.f;
        __nv_bfloat16 hi = __float2bfloat16(w);
        v2h[j] = hi;
        v2l[j] = __float2bfloat16(w - __bfloat162float(hi));
    }
}

// ---------------- fp32 [N,EMB] -> bf16 hi/lo [N,KP1], vectorized x4 ----------------
__global__ void k_split(const float* __restrict__ src, __nv_bfloat16* __restrict__ dh,
                        __nv_bfloat16* __restrict__ dl, int N) {
    int idx = blockIdx.x * blockDim.x + threadIdx.x;          // one per 4 elems
    if (idx >= N * (KP1 / 4)) return;
    int n = idx / (KP1 / 4), k4 = (idx % (KP1 / 4)) * 4;
    float4 v = make_float4(0.f, 0.f, 0.f, 0.f);
    if (k4 < EMB) v = *(const float4*)(src + (size_t)n * EMB + k4);   // EMB%4==0: clean
    __nv_bfloat16 h0 = __float2bfloat16(v.x), h1 = __float2bfloat16(v.y);
    __nv_bfloat16 h2 = __float2bfloat16(v.z), h3 = __float2bfloat16(v.w);
    __nv_bfloat162 hp0, hp1, lp0, lp1;
    hp0.x = h0; hp0.y = h1; hp1.x = h2; hp1.y = h3;
    lp0.x = __float2bfloat16(v.x - __bfloat162float(h0));
    lp0.y = __float2bfloat16(v.y - __bfloat162float(h1));
    lp1.x = __float2bfloat16(v.z - __bfloat162float(h2));
    lp1.y = __float2bfloat16(v.w - __bfloat162float(h3));
    uint2 hw, lw;
    hw.x = *(uint32_t*)&hp0; hw.y = *(uint32_t*)&hp1;
    lw.x = *(uint32_t*)&lp0; lw.y = *(uint32_t*)&lp1;
    *(uint2*)(dh + (size_t)n * KP1 + k4) = hw;
    *(uint2*)(dl + (size_t)n * KP1 + k4) = lw;
}

// ---------------- edge scatter (vector atomics) ----------------
__global__ void k_edge_scatter(const float* __restrict__ h, float* __restrict__ agg,
                               const int* __restrict__ ei, const int* __restrict__ ea,
                               const float* __restrict__ bond_emb, int E) {
    int idx = blockIdx.x * blockDim.x + threadIdx.x;
    if (idx >= E * C4) return;
    int e = idx / C4, c = idx % C4;
    int row = ei[e];
    int col = ei[E + e];
    int a0 = ea[e * 3 + 0], a1 = ea[e * 3 + 1], a2 = ea[e * 3 + 2];
    float4 hv = *(const float4*)(h + (size_t)row * EMB + c * 4);
    float4 b0 = *(const float4*)(bond_emb + (size_t)(0 * BOND_V + a0) * EMB + c * 4);
    float4 b1 = *(const float4*)(bond_emb + (size_t)(1 * BOND_V + a1) * EMB + c * 4);
    float4 b2 = *(const float4*)(bond_emb + (size_t)(2 * BOND_V + a2) * EMB + c * 4);
    float mx = fmaxf(hv.x + b0.x + b1.x + b2.x, 0.f);
    float my = fmaxf(hv.y + b0.y + b1.y + b2.y, 0.f);
    float mz = fmaxf(hv.z + b0.z + b1.z + b2.z, 0.f);
    float mw = fmaxf(hv.w + b0.w + b1.w + b2.w, 0.f);
    REDV4(agg + (size_t)col * EMB + c * 4, mx, my, mz, mw);
}

// ================= bf16-split tensor-core GEMM, 128x128x32, cp.async 2-stage =================
// mode 0: fp32 bn(+relu) -> out_f32
// mode 1: bf16 hi/lo split -> out_hi/out_lo (stride ldo, pads zeroed)
// mode 2: fp32 bn(+relu) -> out_f32 AND out_f32b
// mode 3: fused GIN epilogue: hn = bn+relu; h = hn + vn_next[batch]; out_f32=h;
//         out_f32b = (1+eps_next)*h; pooled += h (vector atomics)
#define MM_BM 128
#define MM_BN 128
#define MM_BK 32
#define ROWB  80
#define SA_H  0
#define SA_L  10240
#define SB_H  20480
#define SB_L  30720
#define STAGE 40960
#define EPI_SC 81920
#define EPI_OF 82432
#define SMEM_TOT 82944

__global__ void __launch_bounds__(256, 2)
k_mma_gemm(const __nv_bfloat16* __restrict__ Ah, const __nv_bfloat16* __restrict__ Al,
           const __nv_bfloat16* __restrict__ Bh, const __nv_bfloat16* __restrict__ Bl,
           const float* __restrict__ bias,
           const float* __restrict__ bng, const float* __restrict__ bnb,
           const float* __restrict__ bnm, const float* __restrict__ bnv,
           float* __restrict__ out_f32, float* __restrict__ out_f32b,
           __nv_bfloat16* __restrict__ out_hi, __nv_bfloat16* __restrict__ out_lo,
           const int* __restrict__ batch, const float* __restrict__ vnp,
           float* __restrict__ pooledp, const float* __restrict__ epsp,
           int M, int Kpad, int Nc, int ldo, int do_relu, int mode) {
    extern __shared__ char sm[];
    const uint32_t smb = smem_u32(sm);
    const int tid = threadIdx.x;
    const int lane = tid & 31;
    const int warp = tid >> 5;
    const int warp_m = warp & 3;
    const int warp_n = warp >> 2;
    const int row0 = blockIdx.y * MM_BM;
    const int col0 = blockIdx.x * MM_BN;

    float* scp = (float*)(sm + EPI_SC);
    float* ofp = (float*)(sm + EPI_OF);
    if (tid < MM_BN) {
        int gn = col0 + tid;
        float s = 0.f, o = 0.f;
        if (gn < Nc) {
            s = bng[gn] * rsqrtf(bnv[gn] + BN_EPS);
            o = bias[gn] * s + bnb[gn] - bnm[gn] * s;
        }
        scp[tid] = s;
        ofp[tid] = o;
    }

    float acc[2][8][4];
#pragma unroll
    for (int mi = 0; mi < 2; mi++)
#pragma unroll
        for (int ci = 0; ci < 8; ci++)
#pragma unroll
            for (int q = 0; q < 4; q++) acc[mi][ci][q] = 0.f;

    const int r0i = tid >> 2, s0i = tid & 3;
    const int r1i = (tid + 256) >> 2, s1i = (tid + 256) & 3;
    const int gmA0 = row0 + r0i, gmA1 = row0 + r1i;
    const int gnB0 = col0 + r0i, gnB1 = col0 + r1i;
    const uint32_t szA0 = (gmA0 < M) ? 16u : 0u, szA1 = (gmA1 < M) ? 16u : 0u;
    const uint32_t szB0 = (gnB0 < Nc) ? 16u : 0u, szB1 = (gnB1 < Nc) ? 16u : 0u;
    const size_t oA0 = (size_t)min(gmA0, M - 1) * Kpad + s0i * 8;
    const size_t oA1 = (size_t)min(gmA1, M - 1) * Kpad + s1i * 8;
    const size_t oB0 = (size_t)min(gnB0, Nc - 1) * Kpad + s0i * 8;
    const size_t oB1 = (size_t)min(gnB1, Nc - 1) * Kpad + s1i * 8;
    const uint32_t dA0 = r0i * ROWB + s0i * 16, dA1 = r1i * ROWB + s1i * 16;

#define ISSUE(ch, st) do { \
    const int _k0 = (ch) * MM_BK; \
    const uint32_t _sb = smb + (st) * STAGE; \
    CP_ASYNC16(_sb + SA_H + dA0, Ah + oA0 + _k0, szA0); \
    CP_ASYNC16(_sb + SA_H + dA1, Ah + oA1 + _k0, szA1); \
    CP_ASYNC16(_sb + SA_L + dA0, Al + oA0 + _k0, szA0); \
    CP_ASYNC16(_sb + SA_L + dA1, Al + oA1 + _k0, szA1); \
    CP_ASYNC16(_sb + SB_H + dA0, Bh + oB0 + _k0, szB0); \
    CP_ASYNC16(_sb + SB_H + dA1, Bh + oB1 + _k0, szB1); \
    CP_ASYNC16(_sb + SB_L + dA0, Bl + oB0 + _k0, szB0); \
    CP_ASYNC16(_sb + SB_L + dA1, Bl + oB1 + _k0, szB1); \
    CP_COMMIT(); \
} while (0)

    const uint32_t aoff = (warp_m * 32 + (lane & 15)) * ROWB + (lane >> 4) * 16;
    const uint32_t boff = (warp_n * 64 + (lane & 7) + ((lane >> 4) << 3)) * ROWB
                        + ((lane >> 3) & 1) * 16;

    const int nk = Kpad / MM_BK;
    ISSUE(0, 0);
    for (int ch = 0; ch < nk; ch++) {
        const int st = ch & 1;
        CP_WAIT0();
        // Single barrier per chunk: reaching it means every warp finished the
        // previous chunk's compute (program order), so issuing into the other
        // stage below is safe, and this chunk's cp.async data is visible.
        __syncthreads();
        if (ch + 1 < nk) ISSUE(ch + 1, st ^ 1);

        const uint32_t a_h = smb + st * STAGE + SA_H;
        const uint32_t a_l = smb + st * STAGE + SA_L;
        const uint32_t b_h = smb + st * STAGE + SB_H;
        const uint32_t b_l = smb + st * STAGE + SB_L;
#pragma unroll
        for (int ks = 0; ks < 2; ks++) {
            const uint32_t ka = ks * 32;
            uint32_t ah0[4], ah1[4], al0[4], al1[4];
            LDSM4(ah0, a_h + aoff + ka);
            LDSM4(ah1, a_h + aoff + 16 * ROWB + ka);
            LDSM4(al0, a_l + aoff + ka);
            LDSM4(al1, a_l + aoff + 16 * ROWB + ka);
#pragma unroll
            for (int half = 0; half < 2; half++) {
                const int h4 = half * 4;
                uint32_t bh[2][4], bl[2][4];
                LDSM4(bh[0], b_h + boff + (half * 32 + 0) * ROWB + ka);
                LDSM4(bh[1], b_h + boff + (half * 32 + 16) * ROWB + ka);
                LDSM4(bl[0], b_l + boff + (half * 32 + 0) * ROWB + ka);
                LDSM4(bl[1], b_l + boff + (half * 32 + 16) * ROWB + ka);
#define COMBO(AF0, AF1, BF) \
                MMA16816(acc[0][h4 + 0], AF0, (BF[0] + 0)); \
                MMA16816(acc[1][h4 + 0], AF1, (BF[0] + 0)); \
                MMA16816(acc[0][h4 + 1], AF0, (BF[0] + 2)); \
                MMA16816(acc[1][h4 + 1], AF1, (BF[0] + 2)); \
                MMA16816(acc[0][h4 + 2], AF0, (BF[1] + 0)); \
                MMA16816(acc[1][h4 + 2], AF1, (BF[1] + 0)); \
                MMA16816(acc[0][h4 + 3], AF0, (BF[1] + 2)); \
                MMA16816(acc[1][h4 + 3], AF1, (BF[1] + 2));
                COMBO(ah0, ah1, bh)
                COMBO(ah0, ah1, bl)
                COMBO(al0, al1, bh)
#undef COMBO
            }
        }
    }

    // ---- epilogue ----
    const int tg = lane >> 2;
    const int np = (lane & 3) * 2;
    const float oe = (mode == 3) ? (1.f + __ldg(epsp)) : 0.f;
#pragma unroll
    for (int mi = 0; mi < 2; mi++) {
        const int rb = row0 + warp_m * 32 + mi * 16 + tg;
        int bA = 0, bB = 0;
        if (mode == 3) {
            bA = (rb < M) ? batch[rb] : 0;
            bB = (rb + 8 < M) ? batch[rb + 8] : 0;
        }
#pragma unroll
        for (int ci8 = 0; ci8 < 8; ci8++) {
            int ci = warp_n * 64 + ci8 * 8 + np;
            int gn = col0 + ci;
            float s0 = scp[ci], s1 = scp[ci + 1];
            float o0 = ofp[ci], o1 = ofp[ci + 1];
#pragma unroll
            for (int hb = 0; hb < 2; hb++) {
                int r = rb + hb * 8;
                if (r >= M) continue;
                float v0 = acc[mi][ci8][hb * 2 + 0] * s0 + o0;
                float v1 = acc[mi][ci8][hb * 2 + 1] * s1 + o1;
                if (do_relu) { v0 = fmaxf(v0, 0.f); v1 = fmaxf(v1, 0.f); }
                if (mode == 1) {
                    if (gn < ldo) {
                        __nv_bfloat16 h0 = __float2bfloat16(v0);
                        __nv_bfloat16 h1 = __float2bfloat16(v1);
                        __nv_bfloat162 hp; hp.x = h0; hp.y = h1;
                        __nv_bfloat162 lp;
                        lp.x = __float2bfloat16(v0 - __bfloat162float(h0));
                        lp.y = __float2bfloat16(v1 - __bfloat162float(h1));
                        *(__nv_bfloat162*)(out_hi + (size_t)r * ldo + gn) = hp;
                        *(__nv_bfloat162*)(out_lo + (size_t)r * ldo + gn) = lp;
                    }
                } else if (mode == 3) {
                    if (gn < Nc) {
                        int b = hb ? bB : bA;
                        float2 vv = *(const float2*)(vnp + (size_t)b * EMB + gn);
                        float h0 = v0 + vv.x;
                        float h1 = v1 + vv.y;
                        float2 hw; hw.x = h0; hw.y = h1;
                        *(float2*)(out_f32 + (size_t)r * Nc + gn) = hw;
                        float2 aw; aw.x = h0 * oe; aw.y = h1 * oe;
                        *(float2*)(out_f32b + (size_t)r * Nc + gn) = aw;
                        REDV2(pooledp + (size_t)b * EMB + gn, h0, h1);
                    }
                } else {
                    if (gn < Nc) {
                        float2 fv; fv.x = v0; fv.y = v1;
                        *(float2*)(out_f32 + (size_t)r * Nc + gn) = fv;
                        if (mode == 2)
                            *(float2*)(out_f32b + (size_t)r * Nc + gn) = fv;
                    }
                }
            }
        }
    }
}

// ---------------- final mean pool ----------------
__global__ void k_final_zero(float* __restrict__ out, float* __restrict__ counts) {
    int idx = blockIdx.x * blockDim.x + threadIdx.x;
    if (idx < NGRAPH * EMB) out[idx] = 0.f;
    if (idx < NGRAPH) counts[idx] = 0.f;
}
__global__ void k_final_acc(const float* __restrict__ h, const int* __restrict__ batch,
                            float* __restrict__ out, float* __restrict__ counts, int N) {
    int idx = blockIdx.x * blockDim.x + threadIdx.x;
    if (idx >= N * C4) return;
    int n = idx / C4, c = idx % C4;
    int b = batch[n];
    float4 hv = *(const float4*)(h + (size_t)n * EMB + c * 4);
    REDV4(out + (size_t)b * EMB + c * 4, hv.x, hv.y, hv.z, hv.w);
    if (c == 0) atomicAdd(counts + b, 1.f);
}
__global__ void k_final_div(float* __restrict__ out, const float* __restrict__ counts) {
    int idx = blockIdx.x * blockDim.x + threadIdx.x;
    if (idx >= NGRAPH * EMB) return;
    int g = idx / EMB;
    out[idx] /= fmaxf(counts[g], 1.f);
}

static inline dim3 mma_grid(int M, int Nc) {
    return dim3((Nc + MM_BN - 1) / MM_BN, (M + MM_BM - 1) / MM_BM);
}

extern "C" void kernel_launch(void* const* d_in, const int* in_sizes, int n_in,
                              void* d_out, int out_size) {
    const int*   x        = (const int*)  d_in[0];
    const int*   ei       = (const int*)  d_in[1];
    const int*   ea       = (const int*)  d_in[2];
    const int*   batch    = (const int*)  d_in[3];
    const float* atom_emb = (const float*)d_in[4];
    const float* bond_emb = (const float*)d_in[5];
    const float* vn_emb   = (const float*)d_in[6];
    const float* gin_eps  = (const float*)d_in[7];
    const float* gin_W1   = (const float*)d_in[8];
    const float* gin_b1   = (const float*)d_in[9];
    const float* gin_bn1_g= (const float*)d_in[10];
    const float* gin_bn1_b= (const float*)d_in[11];
    const float* gin_bn1_m= (const float*)d_in[12];
    const float* gin_bn1_v= (const float*)d_in[13];
    const float* gin_W2   = (const float*)d_in[14];
    const float* gin_b2   = (const float*)d_in[15];
    const float* bn_g     = (const float*)d_in[16];
    const float* bn_b     = (const float*)d_in[17];
    const float* bn_m     = (const float*)d_in[18];
    const float* bn_v     = (const float*)d_in[19];
    const float* vn_W1    = (const float*)d_in[20];
    const float* vn_b1    = (const float*)d_in[21];
    const float* vn_bn1_g = (const float*)d_in[22];
    const float* vn_bn1_b = (const float*)d_in[23];
    const float* vn_bn1_m = (const float*)d_in[24];
    const float* vn_bn1_v = (const float*)d_in[25];
    const float* vn_W2    = (const float*)d_in[26];
    const float* vn_b2    = (const float*)d_in[27];
    const float* vn_bn2_g = (const float*)d_in[28];
    const float* vn_bn2_b = (const float*)d_in[29];
    const float* vn_bn2_m = (const float*)d_in[30];
    const float* vn_bn2_v = (const float*)d_in[31];

    const int N = in_sizes[0] / ATOM_F;
    const int E = in_sizes[1] / 2;
    float* out = (float*)d_out;

    float *h, *agg, *vn, *pooled, *counts;
    __nv_bfloat16 *aggh, *aggl, *t1h, *t1l, *plh, *pll, *vnth, *vntl;
    __nv_bfloat16 *w1h, *w1l, *w2h, *w2l, *v1h, *v1l, *v2h, *v2l;
    cudaGetSymbolAddress((void**)&h,      g_h);
    cudaGetSymbolAddress((void**)&agg,    g_agg);
    cudaGetSymbolAddress((void**)&vn,     g_vn);
    cudaGetSymbolAddress((void**)&pooled, g_pooled);
    cudaGetSymbolAddress((void**)&counts, g_counts);
    cudaGetSymbolAddress((void**)&aggh,   g_agg_h);
    cudaGetSymbolAddress((void**)&aggl,   g_agg_l);
    cudaGetSymbolAddress((void**)&t1h,    g_t1_h);
    cudaGetSymbolAddress((void**)&t1l,    g_t1_l);
    cudaGetSymbolAddress((void**)&plh,    g_pl_h);
    cudaGetSymbolAddress((void**)&pll,    g_pl_l);
    cudaGetSymbolAddress((void**)&vnth,   g_vnt_h);
    cudaGetSymbolAddress((void**)&vntl,   g_vnt_l);
    cudaGetSymbolAddress((void**)&w1h,    g_w1t_h);
    cudaGetSymbolAddress((void**)&w1l,    g_w1t_l);
    cudaGetSymbolAddress((void**)&w2h,    g_w2t_h);
    cudaGetSymbolAddress((void**)&w2l,    g_w2t_l);
    cudaGetSymbolAddress((void**)&v1h,    g_wv1_h);
    cudaGetSymbolAddress((void**)&v1l,    g_wv1_l);
    cudaGetSymbolAddress((void**)&v2h,    g_wv2_h);
    cudaGetSymbolAddress((void**)&v2l,    g_wv2_l);

    cudaFuncSetAttribute(k_mma_gemm, cudaFuncAttributeMaxDynamicSharedMemorySize, SMEM_TOT);

    const int T = 256;
    const int gN  = (N * C4 + T - 1) / T;
    const int gE  = (E * C4 + T - 1) / T;
    const int gVN = (NGRAPH * EMB + T - 1) / T;
    const int gS  = (N * (KP1 / 4) + T - 1) / T;
    const int gSP = (NGRAPH * (KP1 / 4) + T - 1) / T;
    const int WTOT = NLAYERS * 2 * EMB * KP1 + NLAYERS * EMB * KP2
                   + (NLAYERS - 1) * 2 * EMB * KP1 + (NLAYERS - 1) * EMB * KP2;

    // launch order keeps k_edge_scatter at index 3 (ncu slot)
    k_atom_encode<<<gN, T>>>(x, atom_emb, h, N);                       // 0
    k_vn_init<<<gVN, T>>>(vn_emb, vn, pooled);                         // 1
    k_vnadd0<<<gN, T>>>(h, agg, vn_emb, batch, pooled, gin_eps, N);    // 2

    for (int l = 0; l < NLAYERS; l++) {
        const int do_pool = (l < NLAYERS - 1);
        k_edge_scatter<<<gE, T>>>(h, agg, ei, ea, bond_emb, E);        // l=0: 3
        if (l == 0)
            k_prep_w<<<(WTOT + T - 1) / T, T>>>(gin_W1, gin_W2, vn_W1, vn_W2,
                                                w1h, w1l, w2h, w2l, v1h, v1l, v2h, v2l);
        k_split<<<gS, T>>>(agg, aggh, aggl, N);
        // GEMM1: t1(hi/lo) = relu(bn1(agg @ W1 + b1))
        k_mma_gemm<<<mma_grid(N, 2 * EMB), 256, SMEM_TOT>>>(
            aggh, aggl, w1h + (size_t)l * 2 * EMB * KP1, w1l + (size_t)l * 2 * EMB * KP1,
            gin_b1 + l * 2 * EMB,
            gin_bn1_g + l * 2 * EMB, gin_bn1_b + l * 2 * EMB,
            gin_bn1_m + l * 2 * EMB, gin_bn1_v + l * 2 * EMB,
            nullptr, nullptr, t1h, t1l, nullptr, nullptr, nullptr, nullptr,
            N, KP1, 2 * EMB, KP2, 1, 1);
        if (do_pool) {
            // vn MLP (produces vn_{l+1}; mode 2 also resets pooled = vn_{l+1})
            k_split<<<gSP, T>>>(pooled, plh, pll, NGRAPH);
            k_mma_gemm<<<mma_grid(NGRAPH, 2 * EMB), 256, SMEM_TOT>>>(
                plh, pll, v1h + (size_t)l * 2 * EMB * KP1, v1l + (size_t)l * 2 * EMB * KP1,
                vn_b1 + l * 2 * EMB,
                vn_bn1_g + l * 2 * EMB, vn_bn1_b + l * 2 * EMB,
                vn_bn1_m + l * 2 * EMB, vn_bn1_v + l * 2 * EMB,
                nullptr, nullptr, vnth, vntl, nullptr, nullptr, nullptr, nullptr,
                NGRAPH, KP1, 2 * EMB, KP2, 1, 1);
            k_mma_gemm<<<mma_grid(NGRAPH, EMB), 256, SMEM_TOT>>>(
                vnth, vntl, v2h + (size_t)l * EMB * KP2, v2l + (size_t)l * EMB * KP2,
                vn_b2 + l * EMB,
                vn_bn2_g + l * EMB, vn_bn2_b + l * EMB,
                vn_bn2_m + l * EMB, vn_bn2_v + l * EMB,
                vn, pooled, nullptr, nullptr, nullptr, nullptr, nullptr, nullptr,
                NGRAPH, KP2, EMB, EMB, 1, 2);
            // GEMM2 fused (mode 3): h = relu(bn(t1@W2+b2)) + vn_{l+1}[batch];
            // agg = (1+eps_{l+1})*h; pooled += h
            k_mma_gemm<<<mma_grid(N, EMB), 256, SMEM_TOT>>>(
                t1h, t1l, w2h + (size_t)l * EMB * KP2, w2l + (size_t)l * EMB * KP2,
                gin_b2 + l * EMB,
                bn_g + l * EMB, bn_b + l * EMB, bn_m + l * EMB, bn_v + l * EMB,
                h, agg, nullptr, nullptr, batch, vn, pooled, gin_eps + (l + 1),
                N, KP2, EMB, EMB, 1, 3);
        } else {
            // last layer: plain h = bn(t1@W2+b2), no relu
            k_mma_gemm<<<mma_grid(N, EMB), 256, SMEM_TOT>>>(
                t1h, t1l, w2h + (size_t)l * EMB * KP2, w2l + (size_t)l * EMB * KP2,
                gin_b2 + l * EMB,
                bn_g + l * EMB, bn_b + l * EMB, bn_m + l * EMB, bn_v + l * EMB,
                h, nullptr, nullptr, nullptr, nullptr, nullptr, nullptr, nullptr,
                N, KP2, EMB, EMB, 0, 0);
        }
    }

    k_final_zero<<<gVN, T>>>(out, counts);
    k_final_acc<<<gN, T>>>(h, batch, out, counts, N);
    k_final_div<<<gVN, T>>>(out, counts);
}